// round 4
// baseline (speedup 1.0000x reference)
#include <cuda_runtime.h>
#include <cuda_bf16.h>
#include <math.h>

#define BB 32
#define NN 196
#define TT 128
#define DH 512
#define VV 10000
#define GRID_P 148

// ---------------- device scratch (static, no allocation) ----------------
__device__ float g_keys[BB * NN * DH];      // 12.8 MB
__device__ float g_wk  [BB * NN * DH];      // 12.8 MB
__device__ float g_xseq[BB * TT * DH];      // 8.4 MB
__device__ float g_Gx  [BB * TT * 4 * DH];  // 33.6 MB (x-part of gates, biases folded)
__device__ float g_gpart[16 * BB * 4 * DH]; // split-K partials
__device__ float g_hall[BB * TT * DH];      // all h_t, row = b*TT+t
__device__ float g_z   [BB * 1024];         // [ctx | h] per batch
__device__ float g_c   [BB * DH];
__device__ float g_hwh [BB * DH];
__device__ float g_sc  [BB * NN];
__device__ unsigned g_bar[2];               // [0]=count, [1]=generation

__device__ __forceinline__ float fast_tanh(float x) {
    float y; asm("tanh.approx.f32 %0, %1;" : "=f"(y) : "f"(x)); return y;
}
__device__ __forceinline__ float sigm(float x) { return 1.f / (1.f + expf(-x)); }

// ---------------- generic SGEMM: C[M,N] = A[M,K] @ B[N,K]^T (+b1[n]+b2[n]) ----------------
__global__ __launch_bounds__(256) void gemm_nt(
    const float* __restrict__ A, int lda,
    const float* __restrict__ B, int ldb,
    const float* __restrict__ bias1, const float* __restrict__ bias2,
    float* __restrict__ C, int ldc, int M, int N, int K)
{
    __shared__ float As[8][128];
    __shared__ float Bs[8][128];
    const int tid = threadIdx.x;
    const int mBase = blockIdx.y * 128;
    const int nBase = blockIdx.x * 128;
    const int lr = tid >> 1;
    const int lc = (tid & 1) * 4;
    const int ty = tid >> 4;
    const int tx = tid & 15;

    float acc[8][8];
#pragma unroll
    for (int i = 0; i < 8; i++)
#pragma unroll
        for (int j = 0; j < 8; j++) acc[i][j] = 0.f;

    const bool aval = (mBase + lr) < M;
    const bool bval = (nBase + lr) < N;
    const float* Aptr = A + (size_t)(mBase + lr) * lda + lc;
    const float* Bptr = B + (size_t)(nBase + lr) * ldb + lc;

    for (int k0 = 0; k0 < K; k0 += 8) {
        float4 av = make_float4(0.f, 0.f, 0.f, 0.f);
        float4 bv = make_float4(0.f, 0.f, 0.f, 0.f);
        if (aval) av = *(const float4*)(Aptr + k0);
        if (bval) bv = *(const float4*)(Bptr + k0);
        As[lc + 0][lr] = av.x; As[lc + 1][lr] = av.y;
        As[lc + 2][lr] = av.z; As[lc + 3][lr] = av.w;
        Bs[lc + 0][lr] = bv.x; Bs[lc + 1][lr] = bv.y;
        Bs[lc + 2][lr] = bv.z; Bs[lc + 3][lr] = bv.w;
        __syncthreads();
#pragma unroll
        for (int kk = 0; kk < 8; kk++) {
            float a[8], b[8];
            *(float4*)&a[0] = *(const float4*)&As[kk][ty * 8];
            *(float4*)&a[4] = *(const float4*)&As[kk][ty * 8 + 4];
            *(float4*)&b[0] = *(const float4*)&Bs[kk][tx * 8];
            *(float4*)&b[4] = *(const float4*)&Bs[kk][tx * 8 + 4];
#pragma unroll
            for (int i = 0; i < 8; i++)
#pragma unroll
                for (int j = 0; j < 8; j++)
                    acc[i][j] = fmaf(a[i], b[j], acc[i][j]);
        }
        __syncthreads();
    }

#pragma unroll
    for (int i = 0; i < 8; i++) {
        const int gm = mBase + ty * 8 + i;
        if (gm >= M) continue;
#pragma unroll
        for (int j = 0; j < 8; j++) {
            const int gn = nBase + tx * 8 + j;
            if (gn < N) {
                float v = acc[i][j];
                if (bias1) v += bias1[gn];
                if (bias2) v += bias2[gn];
                C[(size_t)gm * ldc + gn] = v;
            }
        }
    }
}

// ---------------- embedding gather ----------------
__global__ void gather_x(const int* __restrict__ ids, const float* __restrict__ emb)
{
    const int i = blockIdx.x * 256 + threadIdx.x;
    if (i < BB * TT * DH) {
        const int d = i & (DH - 1);
        const int bt = i >> 9;
        g_xseq[i] = emb[(size_t)ids[bt] * DH + d];
    }
}

// ---------------- persistent decode loop ----------------
__global__ __launch_bounds__(256) void decode_loop(
    const float* __restrict__ Wh, const float* __restrict__ av,
    const float* __restrict__ Wih, const float* __restrict__ Whh,
    const float* __restrict__ lnw, const float* __restrict__ lnb)
{
    __shared__ float Zs[32][65];
    __shared__ float Ws[128][65];
    __shared__ float s_sc[NN + 4];
    __shared__ float s_r0[8], s_r1[8], s_mv[2];

    const int tid = threadIdx.x;
    const int bid = blockIdx.x;
    const int warp = tid >> 5, lane = tid & 31;
    const int gwarp = bid * 8 + warp;
    unsigned bt = 0;

    // grid barrier: fence + relaxed atomics, monotone generation
    auto gsync = [&](unsigned target) {
        __syncthreads();
        if (tid == 0) {
            __threadfence();
            unsigned a = atomicAdd(&g_bar[0], 1u);
            if (a == target * GRID_P - 1u) {
                atomicExch(&g_bar[1], target);
            } else {
                while (atomicAdd(&g_bar[1], 0u) < target) { __nanosleep(32); }
            }
            __threadfence();
        }
        __syncthreads();
    };

    for (int t = 0; t < TT; t++) {
        // ---- P1: hwh[b][d] = dot(h[b], Wh[d]) ; warp per (b,d) ----
        for (int j = gwarp; j < BB * DH; j += GRID_P * 8) {
            const int b = j >> 9, d = j & (DH - 1);
            const float4* w4 = (const float4*)(Wh + (size_t)d * DH);
            const float4* h4 = (const float4*)(g_z + b * 1024 + 512);
            float acc = 0.f;
#pragma unroll
            for (int i = 0; i < 4; i++) {
                float4 w = w4[lane + 32 * i];
                float4 h = h4[lane + 32 * i];
                acc += w.x * h.x + w.y * h.y + w.z * h.z + w.w * h.w;
            }
#pragma unroll
            for (int o = 16; o; o >>= 1) acc += __shfl_xor_sync(0xffffffffu, acc, o);
            if (lane == 0) g_hwh[b * DH + d] = acc;
        }
        gsync(++bt);

        // ---- P2: scores[b][n] = sum_d tanh(hwh+wk)*v ; warp per (b,n) ----
        for (int j = gwarp; j < BB * NN; j += GRID_P * 8) {
            const int b = j / NN, n = j - b * NN;
            const float4* wk4 = (const float4*)(g_wk + ((size_t)b * NN + n) * DH);
            const float4* hw4 = (const float4*)(g_hwh + b * DH);
            const float4* v4  = (const float4*)av;
            float s = 0.f;
#pragma unroll
            for (int i = 0; i < 4; i++) {
                float4 a = wk4[lane + 32 * i];
                float4 c = hw4[lane + 32 * i];
                float4 w = v4[lane + 32 * i];
                s += fast_tanh(a.x + c.x) * w.x + fast_tanh(a.y + c.y) * w.y +
                     fast_tanh(a.z + c.z) * w.z + fast_tanh(a.w + c.w) * w.w;
            }
#pragma unroll
            for (int o = 16; o; o >>= 1) s += __shfl_xor_sync(0xffffffffu, s, o);
            if (lane == 0) g_sc[b * NN + n] = s;
        }
        gsync(++bt);

        // ---- P3: softmax + ctx ; block per batch (blocks 0..31) ----
        if (bid < BB) {
            const int b = bid;
            float x = (tid < NN) ? g_sc[b * NN + tid] : -1e30f;
            float m = x;
#pragma unroll
            for (int o = 16; o; o >>= 1) m = fmaxf(m, __shfl_xor_sync(0xffffffffu, m, o));
            if (lane == 0) s_r0[warp] = m;
            __syncthreads();
            if (tid < 8) {
                float v = s_r0[tid];
#pragma unroll
                for (int o = 4; o; o >>= 1) v = fmaxf(v, __shfl_xor_sync(0x000000ffu, v, o));
                if (tid == 0) s_mv[0] = v;
            }
            __syncthreads();
            const float bm = s_mv[0];
            __syncthreads();
            float e = (tid < NN) ? __expf(x - bm) : 0.f;
            float s = e;
#pragma unroll
            for (int o = 16; o; o >>= 1) s += __shfl_xor_sync(0xffffffffu, s, o);
            if (lane == 0) s_r0[warp] = s;
            __syncthreads();
            if (tid < 8) {
                float v = s_r0[tid];
#pragma unroll
                for (int o = 4; o; o >>= 1) v += __shfl_xor_sync(0x000000ffu, v, o);
                if (tid == 0) s_mv[1] = v;
            }
            __syncthreads();
            const float inv = 1.f / s_mv[1];
            if (tid < NN) s_sc[tid] = e * inv;
            __syncthreads();

#pragma unroll
            for (int u = 0; u < 2; u++) {
                const int d = tid + u * 256;
                const float* Kp = g_keys + (size_t)b * NN * DH + d;
                float a0 = 0.f, a1 = 0.f, a2 = 0.f, a3 = 0.f;
                for (int n = 0; n < NN; n += 4) {
                    a0 += s_sc[n + 0] * Kp[(size_t)(n + 0) * DH];
                    a1 += s_sc[n + 1] * Kp[(size_t)(n + 1) * DH];
                    a2 += s_sc[n + 2] * Kp[(size_t)(n + 2) * DH];
                    a3 += s_sc[n + 3] * Kp[(size_t)(n + 3) * DH];
                }
                g_z[b * 1024 + d] = (a0 + a1) + (a2 + a3);
            }
        }
        gsync(++bt);

        // ---- P4: split-K gates ; jobs (16 ntiles x 16 ksplits) over all blocks ----
        for (int job = bid; job < 256; job += GRID_P) {
            const int ntile = job & 15;
            const int ks = job >> 4;
            const int nBase = ntile * 128;
            const int koff = ks * 64;
            const float* Wsrc; int ldw, coff;
            if (ks < 8) { Wsrc = Wih; ldw = 1024; coff = 512 + koff; }
            else        { Wsrc = Whh; ldw = 512;  coff = koff - 512; }

            {
                const int r = tid >> 3, c = (tid & 7) * 8;
                const float* src = g_z + r * 1024 + koff + c;
                float4 v0 = *(const float4*)src;
                float4 v1 = *(const float4*)(src + 4);
                Zs[r][c + 0] = v0.x; Zs[r][c + 1] = v0.y; Zs[r][c + 2] = v0.z; Zs[r][c + 3] = v0.w;
                Zs[r][c + 4] = v1.x; Zs[r][c + 5] = v1.y; Zs[r][c + 6] = v1.z; Zs[r][c + 7] = v1.w;
            }
            {
                const int r0 = tid >> 2, c = (tid & 3) * 16;
#pragma unroll
                for (int rr = 0; rr < 128; rr += 64) {
                    const int r = r0 + rr;
                    const float* src = Wsrc + (size_t)(nBase + r) * ldw + coff + c;
#pragma unroll
                    for (int jj = 0; jj < 16; jj += 4) {
                        float4 v = *(const float4*)(src + jj);
                        Ws[r][c + jj + 0] = v.x; Ws[r][c + jj + 1] = v.y;
                        Ws[r][c + jj + 2] = v.z; Ws[r][c + jj + 3] = v.w;
                    }
                }
            }
            __syncthreads();

            const int ty = tid >> 5, tx = tid & 31;
            float acc[4][4];
#pragma unroll
            for (int i = 0; i < 4; i++)
#pragma unroll
                for (int j = 0; j < 4; j++) acc[i][j] = 0.f;

#pragma unroll 8
            for (int kk = 0; kk < 64; kk++) {
                float z[4], w[4];
#pragma unroll
                for (int i = 0; i < 4; i++) z[i] = Zs[4 * ty + i][kk];
#pragma unroll
                for (int j = 0; j < 4; j++) w[j] = Ws[tx + 32 * j][kk];
#pragma unroll
                for (int i = 0; i < 4; i++)
#pragma unroll
                    for (int j = 0; j < 4; j++)
                        acc[i][j] = fmaf(z[i], w[j], acc[i][j]);
            }

            float* dst = g_gpart + ((size_t)ks * 32 + 4 * ty) * 2048 + nBase + tx;
#pragma unroll
            for (int i = 0; i < 4; i++)
#pragma unroll
                for (int j = 0; j < 4; j++)
                    dst[(size_t)i * 2048 + 32 * j] = acc[i][j];
            __syncthreads();
        }
        gsync(++bt);

        // ---- P5: cell + LayerNorm ; block per batch ----
        if (bid < BB) {
            const int b = bid;
            float hr[2];
            float sum = 0.f, ssq = 0.f;
            const float* Gx = g_Gx + (size_t)(b * TT + t) * 2048;
#pragma unroll
            for (int u = 0; u < 2; u++) {
                const int d = tid + u * 256;
                float gi = Gx[d], gf = Gx[512 + d], gg = Gx[1024 + d], go = Gx[1536 + d];
#pragma unroll
                for (int s = 0; s < 16; s++) {
                    const float* P = g_gpart + ((size_t)s * 32 + b) * 2048;
                    gi += P[d]; gf += P[512 + d]; gg += P[1024 + d]; go += P[1536 + d];
                }
                const float c_old = g_c[b * DH + d];
                const float cn = sigm(gf) * c_old + sigm(gi) * tanhf(gg);
                g_c[b * DH + d] = cn;
                const float h = sigm(go) * tanhf(cn);
                hr[u] = h; sum += h; ssq += h * h;
            }
#pragma unroll
            for (int o = 16; o; o >>= 1) {
                sum += __shfl_xor_sync(0xffffffffu, sum, o);
                ssq += __shfl_xor_sync(0xffffffffu, ssq, o);
            }
            if (lane == 0) { s_r0[warp] = sum; s_r1[warp] = ssq; }
            __syncthreads();
            if (tid < 8) {
                float s = s_r0[tid], q = s_r1[tid];
#pragma unroll
                for (int o = 4; o; o >>= 1) {
                    s += __shfl_xor_sync(0x000000ffu, s, o);
                    q += __shfl_xor_sync(0x000000ffu, q, o);
                }
                if (tid == 0) { s_mv[0] = s * (1.f / DH); s_mv[1] = q * (1.f / DH); }
            }
            __syncthreads();
            const float mu = s_mv[0];
            const float var = s_mv[1] - mu * mu;
            const float rstd = rsqrtf(var + 1e-5f);
#pragma unroll
            for (int u = 0; u < 2; u++) {
                const int d = tid + u * 256;
                const float h = (hr[u] - mu) * rstd * lnw[d] + lnb[d];
                g_z[b * 1024 + 512 + d] = h;
                g_hall[(size_t)(b * TT + t) * DH + d] = h;
            }
        }
        gsync(++bt);
    }
}

// ---------------- launch ----------------
extern "C" void kernel_launch(void* const* d_in, const int* in_sizes, int n_in,
                              void* d_out, int out_size)
{
    const float* patches = (const float*)d_in[0];
    const float* cls     = (const float*)d_in[1];
    const int*   tgt     = (const int*)  d_in[2];
    const float* emb     = (const float*)d_in[3];
    const float* kvW     = (const float*)d_in[4];
    const float* kvb     = (const float*)d_in[5];
    const float* ihW     = (const float*)d_in[6];
    const float* ihb     = (const float*)d_in[7];
    const float* icW     = (const float*)d_in[8];
    const float* icb     = (const float*)d_in[9];
    const float* aWh     = (const float*)d_in[10];
    const float* aWk     = (const float*)d_in[11];
    const float* av      = (const float*)d_in[12];
    const float* Wih     = (const float*)d_in[13];
    const float* Whh     = (const float*)d_in[14];
    const float* bih     = (const float*)d_in[15];
    const float* bhh     = (const float*)d_in[16];
    const float* lnw     = (const float*)d_in[17];
    const float* lnb     = (const float*)d_in[18];
    const float* outW    = (const float*)d_in[19];
    const float* outb    = (const float*)d_in[20];
    float* out = (float*)d_out;

    float *keys, *wk, *xseq, *Gx, *z, *c, *hall;
    unsigned* barp;
    cudaGetSymbolAddress((void**)&keys, g_keys);
    cudaGetSymbolAddress((void**)&wk,   g_wk);
    cudaGetSymbolAddress((void**)&xseq, g_xseq);
    cudaGetSymbolAddress((void**)&Gx,   g_Gx);
    cudaGetSymbolAddress((void**)&z,    g_z);
    cudaGetSymbolAddress((void**)&c,    g_c);
    cudaGetSymbolAddress((void**)&hall, g_hall);
    cudaGetSymbolAddress((void**)&barp, g_bar);

    // reset grid-barrier state (graph-capturable memset node)
    cudaMemsetAsync(barp, 0, 2 * sizeof(unsigned));

    // pre-loop
    gather_x<<<(BB * TT * DH) / 256, 256>>>(tgt, emb);
    gemm_nt<<<dim3(4, 49), 256>>>(patches, 768, kvW, 768, kvb, nullptr, keys, 512, BB * NN, 512, 768);
    gemm_nt<<<dim3(4, 49), 256>>>(keys, 512, aWk, 512, nullptr, nullptr, wk, 512, BB * NN, 512, 512);
    gemm_nt<<<dim3(4, 1), 256>>>(cls, 768, ihW, 768, ihb, nullptr, z + 512, 1024, BB, 512, 768);
    gemm_nt<<<dim3(4, 1), 256>>>(cls, 768, icW, 768, icb, nullptr, c, 512, BB, 512, 768);
    gemm_nt<<<dim3(16, 32), 256>>>(xseq, 512, Wih, 1024, bih, bhh, Gx, 2048, BB * TT, 2048, 512);

    // fused sequential decode loop (one persistent kernel, software grid barriers)
    decode_loop<<<GRID_P, 256>>>(aWh, av, Wih, Whh, lnw, lnb);

    // deferred logits: [4096, 10000] = hall @ outW^T + outb
    gemm_nt<<<dim3(79, 32), 256>>>(hall, 512, outW, 512, outb, nullptr, out, VV, BB * TT, VV, 512);
}

// round 5
// speedup vs baseline: 1.1090x; 1.1090x over previous
#include <cuda_runtime.h>
#include <cuda_bf16.h>
#include <math.h>

#define BB 32
#define NN 196
#define TT 128
#define DH 512
#define VV 10000
#define GRID_P 148
#define NCH 4      // softmax n-chunks
#define CHN 49     // n per chunk (196 = 4*49)

// ---------------- device scratch (static, no allocation) ----------------
__device__ float g_keys[BB * NN * DH];
__device__ float g_wk  [BB * NN * DH];
__device__ float g_xseq[BB * TT * DH];
__device__ float g_Gx  [BB * TT * 4 * DH];
__device__ float g_gpart[8 * BB * 4 * DH];   // 8 k-split partials of gates
__device__ float g_hall[BB * TT * DH];
__device__ float g_z   [BB * 1024];          // h lives at +512 per batch
__device__ float g_c   [BB * DH];
__device__ float g_hwh [BB * DH];
__device__ float g_ctxp[NCH * BB * DH];      // partial (unnormalized) ctx
__device__ float g_cm  [BB * NCH];           // chunk max
__device__ float g_cs  [BB * NCH];           // chunk exp-sum
__device__ unsigned g_bar[2];                // [0]=arrive count, [1]=generation

__device__ __forceinline__ float fast_tanh(float x) {
    float y; asm("tanh.approx.f32 %0, %1;" : "=f"(y) : "f"(x)); return y;
}
__device__ __forceinline__ float sigm(float x) { return 1.f / (1.f + expf(-x)); }

// ---------------- generic SGEMM: C[M,N] = A[M,K] @ B[N,K]^T (+b1[n]+b2[n]) ----------------
__global__ __launch_bounds__(256) void gemm_nt(
    const float* __restrict__ A, int lda,
    const float* __restrict__ B, int ldb,
    const float* __restrict__ bias1, const float* __restrict__ bias2,
    float* __restrict__ C, int ldc, int M, int N, int K)
{
    __shared__ float As[8][128];
    __shared__ float Bs[8][128];
    const int tid = threadIdx.x;
    const int mBase = blockIdx.y * 128;
    const int nBase = blockIdx.x * 128;
    const int lr = tid >> 1;
    const int lc = (tid & 1) * 4;
    const int ty = tid >> 4;
    const int tx = tid & 15;

    float acc[8][8];
#pragma unroll
    for (int i = 0; i < 8; i++)
#pragma unroll
        for (int j = 0; j < 8; j++) acc[i][j] = 0.f;

    const bool aval = (mBase + lr) < M;
    const bool bval = (nBase + lr) < N;
    const float* Aptr = A + (size_t)(mBase + lr) * lda + lc;
    const float* Bptr = B + (size_t)(nBase + lr) * ldb + lc;

    for (int k0 = 0; k0 < K; k0 += 8) {
        float4 av = make_float4(0.f, 0.f, 0.f, 0.f);
        float4 bv = make_float4(0.f, 0.f, 0.f, 0.f);
        if (aval) av = *(const float4*)(Aptr + k0);
        if (bval) bv = *(const float4*)(Bptr + k0);
        As[lc + 0][lr] = av.x; As[lc + 1][lr] = av.y;
        As[lc + 2][lr] = av.z; As[lc + 3][lr] = av.w;
        Bs[lc + 0][lr] = bv.x; Bs[lc + 1][lr] = bv.y;
        Bs[lc + 2][lr] = bv.z; Bs[lc + 3][lr] = bv.w;
        __syncthreads();
#pragma unroll
        for (int kk = 0; kk < 8; kk++) {
            float a[8], b[8];
            *(float4*)&a[0] = *(const float4*)&As[kk][ty * 8];
            *(float4*)&a[4] = *(const float4*)&As[kk][ty * 8 + 4];
            *(float4*)&b[0] = *(const float4*)&Bs[kk][tx * 8];
            *(float4*)&b[4] = *(const float4*)&Bs[kk][tx * 8 + 4];
#pragma unroll
            for (int i = 0; i < 8; i++)
#pragma unroll
                for (int j = 0; j < 8; j++)
                    acc[i][j] = fmaf(a[i], b[j], acc[i][j]);
        }
        __syncthreads();
    }

#pragma unroll
    for (int i = 0; i < 8; i++) {
        const int gm = mBase + ty * 8 + i;
        if (gm >= M) continue;
#pragma unroll
        for (int j = 0; j < 8; j++) {
            const int gn = nBase + tx * 8 + j;
            if (gn < N) {
                float v = acc[i][j];
                if (bias1) v += bias1[gn];
                if (bias2) v += bias2[gn];
                C[(size_t)gm * ldc + gn] = v;
            }
        }
    }
}

// ---------------- embedding gather ----------------
__global__ void gather_x(const int* __restrict__ ids, const float* __restrict__ emb)
{
    const int i = blockIdx.x * 256 + threadIdx.x;
    if (i < BB * TT * DH) {
        const int d = i & (DH - 1);
        const int bt = i >> 9;
        g_xseq[i] = emb[(size_t)ids[bt] * DH + d];
    }
}

// ---------------- h0/c0: spread warp-per-dot (both matrices, one kernel) ----------------
__global__ __launch_bounds__(256) void h0c0_kernel(
    const float* __restrict__ cls,
    const float* __restrict__ ihW, const float* __restrict__ ihb,
    const float* __restrict__ icW, const float* __restrict__ icb)
{
    const int gw = blockIdx.x * 8 + (threadIdx.x >> 5);
    const int lane = threadIdx.x & 31;
    for (int j = gw; j < 2 * BB * DH; j += GRID_P * 8) {
        const int sel = (j >= BB * DH);
        const int r = sel ? j - BB * DH : j;
        const int b = r >> 9, d = r & (DH - 1);
        const float4* W4 = (const float4*)((sel ? icW : ihW) + (size_t)d * 768);
        const float4* x4 = (const float4*)(cls + (size_t)b * 768);
        float acc = 0.f;
#pragma unroll
        for (int q = 0; q < 6; q++) {
            float4 w = W4[lane + 32 * q];
            float4 x = x4[lane + 32 * q];
            acc += w.x * x.x + w.y * x.y + w.z * x.z + w.w * x.w;
        }
#pragma unroll
        for (int o = 16; o; o >>= 1) acc += __shfl_xor_sync(0xffffffffu, acc, o);
        if (lane == 0) {
            if (sel) g_c[b * DH + d] = acc + icb[d];
            else     g_z[b * 1024 + 512 + d] = acc + ihb[d];
        }
    }
}

// ---------------- persistent decode loop ----------------
__global__ __launch_bounds__(256) void decode_loop(
    const float* __restrict__ Wh, const float* __restrict__ av,
    const float* __restrict__ Wih, const float* __restrict__ Whh,
    const float* __restrict__ lnw, const float* __restrict__ lnb)
{
    __shared__ float Zs[64][32];     // k-major z tile
    __shared__ float Ws[64][128];    // k-major weight tile
    __shared__ float s_sc[CHN];
    __shared__ float s_e[64];        // exp weights (only first CHN used)
    __shared__ float s_r0[8], s_r1[8], s_mv[2];

    const int tid = threadIdx.x;
    const int bid = blockIdx.x;
    const int warp = tid >> 5, lane = tid & 31;
    const int gwarp = bid * 8 + warp;
    unsigned bt = 0;

    // grid barrier: atomic arrive, VOLATILE-LOAD poll (no RMW spin), atomic release
    auto gsync = [&](unsigned target) {
        __syncthreads();
        if (tid == 0) {
            __threadfence();
            unsigned a = atomicAdd(&g_bar[0], 1u);
            if (a == target * GRID_P - 1u) {
                atomicExch(&g_bar[1], target);
            } else {
                while (*(volatile unsigned*)&g_bar[1] < target) { __nanosleep(32); }
            }
            __threadfence();
        }
        __syncthreads();
    };

    // hwh spread phase (as lambda: used pre-loop for h0 and as phase E each step)
    auto hwh_phase = [&]() {
        const float4* v_dummy = nullptr; (void)v_dummy;
        for (int j = gwarp; j < BB * DH; j += GRID_P * 8) {
            const int b = j >> 9, d = j & (DH - 1);
            const float4* w4 = (const float4*)(Wh + (size_t)d * DH);
            const float4* h4 = (const float4*)(g_z + b * 1024 + 512);
            float acc = 0.f;
#pragma unroll
            for (int i = 0; i < 4; i++) {
                float4 w = w4[lane + 32 * i];
                float4 h = h4[lane + 32 * i];
                acc += w.x * h.x + w.y * h.y + w.z * h.z + w.w * h.w;
            }
#pragma unroll
            for (int o = 16; o; o >>= 1) acc += __shfl_xor_sync(0xffffffffu, acc, o);
            if (lane == 0) g_hwh[b * DH + d] = acc;
        }
    };

    // pre-loop: hwh for h0
    hwh_phase();
    gsync(++bt);

    for (int t = 0; t < TT; t++) {
        // ---- Phase B: chunk scores + local softmax stats + partial ctx ----
        // 128 jobs: (b, chunk p). No dependence between jobs.
        if (bid < BB * NCH) {
            const int b = bid >> 2, p = bid & 3;
            const float4* hw4 = (const float4*)(g_hwh + b * DH);
            const float4* v4  = (const float4*)av;
            for (int i = warp; i < CHN; i += 8) {
                const int n = p * CHN + i;
                const float4* wk4 = (const float4*)(g_wk + ((size_t)b * NN + n) * DH);
                float s = 0.f;
#pragma unroll
                for (int q = 0; q < 4; q++) {
                    float4 a = wk4[lane + 32 * q];
                    float4 c = hw4[lane + 32 * q];
                    float4 w = v4[lane + 32 * q];
                    s += fast_tanh(a.x + c.x) * w.x + fast_tanh(a.y + c.y) * w.y +
                         fast_tanh(a.z + c.z) * w.z + fast_tanh(a.w + c.w) * w.w;
                }
#pragma unroll
                for (int o = 16; o; o >>= 1) s += __shfl_xor_sync(0xffffffffu, s, o);
                if (lane == 0) s_sc[i] = s;
            }
            __syncthreads();

            // chunk max
            float x = (tid < CHN) ? s_sc[tid] : -1e30f;
            float m = x;
#pragma unroll
            for (int o = 16; o; o >>= 1) m = fmaxf(m, __shfl_xor_sync(0xffffffffu, m, o));
            if (lane == 0) s_r0[warp] = m;
            __syncthreads();
            if (tid < 8) {
                float v = s_r0[tid];
#pragma unroll
                for (int o = 4; o; o >>= 1) v = fmaxf(v, __shfl_xor_sync(0x000000ffu, v, o));
                if (tid == 0) s_mv[0] = v;
            }
            __syncthreads();
            const float mc = s_mv[0];

            float e = (tid < CHN) ? __expf(x - mc) : 0.f;
            if (tid < CHN) s_e[tid] = e;
            float ssum = e;
#pragma unroll
            for (int o = 16; o; o >>= 1) ssum += __shfl_xor_sync(0xffffffffu, ssum, o);
            if (lane == 0) s_r1[warp] = ssum;
            __syncthreads();
            if (tid < 8) {
                float v = s_r1[tid];
#pragma unroll
                for (int o = 4; o; o >>= 1) v += __shfl_xor_sync(0x000000ffu, v, o);
                if (tid == 0) {
                    g_cm[b * NCH + p] = mc;
                    g_cs[b * NCH + p] = v;
                }
            }
            __syncthreads();

            // partial ctx (unnormalized): v_p[d] = sum_{n in chunk} e_n * keys[b,n,d]
#pragma unroll
            for (int u = 0; u < 2; u++) {
                const int d = tid + u * 256;
                const float* Kp = g_keys + ((size_t)b * NN + p * CHN) * DH + d;
                float a0 = 0.f;
#pragma unroll 7
                for (int i = 0; i < CHN; i++)
                    a0 += s_e[i] * Kp[(size_t)i * DH];
                g_ctxp[((size_t)p * BB + b) * DH + d] = a0;
            }
        }
        gsync(++bt);

        // ---- Phase C: gates GEMM, 128 balanced jobs = (gtile 0..15) x (ks2 0..7) ----
        // job covers 128 gate-cols x 128 k, done as two 64-k halves into one acc.
        if (bid < 128) {
            const int gt = bid & 15, ks2 = bid >> 4;
            const int gBase = gt * 128;
            const int bq = tid >> 5, gq = tid & 31;
            float acc[4][4];
#pragma unroll
            for (int i = 0; i < 4; i++)
#pragma unroll
                for (int j = 0; j < 4; j++) acc[i][j] = 0.f;

#pragma unroll
            for (int half = 0; half < 2; half++) {
                const int koff = ks2 * 128 + half * 64;   // global k in [0,1024)
                // load W tile k-major: Ws[kk][g]
                {
                    const float* Wsrc; int ldw, coff;
                    if (koff < 512) { Wsrc = Wih; ldw = 1024; coff = 512 + koff; }
                    else            { Wsrc = Whh; ldw = 512;  coff = koff - 512; }
                    const int g = tid >> 1, kh = (tid & 1) * 32;
                    const float* src = Wsrc + (size_t)(gBase + g) * ldw + coff + kh;
#pragma unroll
                    for (int i = 0; i < 32; i += 4) {
                        float4 v = *(const float4*)(src + i);
                        Ws[kh + i + 0][g] = v.x; Ws[kh + i + 1][g] = v.y;
                        Ws[kh + i + 2][g] = v.z; Ws[kh + i + 3][g] = v.w;
                    }
                }
                // load z tile k-major: Zs[kk][b] (ctx half uses flash-combine)
                {
                    const int b = tid >> 3, kc = (tid & 7) * 8;
                    if (koff < 512) {
                        const float m0 = g_cm[b * NCH + 0], m1 = g_cm[b * NCH + 1];
                        const float m2 = g_cm[b * NCH + 2], m3 = g_cm[b * NCH + 3];
                        const float m = fmaxf(fmaxf(m0, m1), fmaxf(m2, m3));
                        const float e0 = __expf(m0 - m), e1 = __expf(m1 - m);
                        const float e2 = __expf(m2 - m), e3 = __expf(m3 - m);
                        const float den = e0 * g_cs[b * NCH + 0] + e1 * g_cs[b * NCH + 1] +
                                          e2 * g_cs[b * NCH + 2] + e3 * g_cs[b * NCH + 3];
                        const float inv = 1.f / den;
                        const float* c0p = g_ctxp + ((size_t)0 * BB + b) * DH + koff + kc;
                        const float* c1p = g_ctxp + ((size_t)1 * BB + b) * DH + koff + kc;
                        const float* c2p = g_ctxp + ((size_t)2 * BB + b) * DH + koff + kc;
                        const float* c3p = g_ctxp + ((size_t)3 * BB + b) * DH + koff + kc;
#pragma unroll
                        for (int i = 0; i < 8; i++) {
                            float v = e0 * c0p[i] + e1 * c1p[i] + e2 * c2p[i] + e3 * c3p[i];
                            Zs[kc + i][b] = v * inv;
                        }
                    } else {
                        const float* src = g_z + b * 1024 + 512 + (koff - 512) + kc;
                        float4 v0 = *(const float4*)src;
                        float4 v1 = *(const float4*)(src + 4);
                        Zs[kc + 0][b] = v0.x; Zs[kc + 1][b] = v0.y;
                        Zs[kc + 2][b] = v0.z; Zs[kc + 3][b] = v0.w;
                        Zs[kc + 4][b] = v1.x; Zs[kc + 5][b] = v1.y;
                        Zs[kc + 6][b] = v1.z; Zs[kc + 7][b] = v1.w;
                    }
                }
                __syncthreads();

#pragma unroll 16
                for (int kk = 0; kk < 64; kk++) {
                    const float4 z4 = *(const float4*)&Zs[kk][bq * 4];
                    const float4 w4 = *(const float4*)&Ws[kk][gq * 4];
                    const float za[4] = { z4.x, z4.y, z4.z, z4.w };
                    const float wa[4] = { w4.x, w4.y, w4.z, w4.w };
#pragma unroll
                    for (int i = 0; i < 4; i++)
#pragma unroll
                        for (int j = 0; j < 4; j++)
                            acc[i][j] = fmaf(za[i], wa[j], acc[i][j]);
                }
                __syncthreads();
            }

#pragma unroll
            for (int i = 0; i < 4; i++) {
                float4 o = make_float4(acc[i][0], acc[i][1], acc[i][2], acc[i][3]);
                *(float4*)&g_gpart[((size_t)ks2 * BB + bq * 4 + i) * 2048 + gBase + gq * 4] = o;
            }
        }
        gsync(++bt);

        // ---- Phase D: cell + LayerNorm (32 blocks) ----
        if (bid < BB) {
            const int b = bid;
            float hr[2];
            float sum = 0.f, ssq = 0.f;
            const float* Gx = g_Gx + (size_t)(b * TT + t) * 2048;
#pragma unroll
            for (int u = 0; u < 2; u++) {
                const int d = tid + u * 256;
                float gi = Gx[d], gf = Gx[512 + d], gg = Gx[1024 + d], go = Gx[1536 + d];
#pragma unroll
                for (int s = 0; s < 8; s++) {
                    const float* P = g_gpart + ((size_t)s * BB + b) * 2048;
                    gi += P[d]; gf += P[512 + d]; gg += P[1024 + d]; go += P[1536 + d];
                }
                const float c_old = g_c[b * DH + d];
                const float cn = sigm(gf) * c_old + sigm(gi) * tanhf(gg);
                g_c[b * DH + d] = cn;
                const float h = sigm(go) * tanhf(cn);
                hr[u] = h; sum += h; ssq += h * h;
            }
#pragma unroll
            for (int o = 16; o; o >>= 1) {
                sum += __shfl_xor_sync(0xffffffffu, sum, o);
                ssq += __shfl_xor_sync(0xffffffffu, ssq, o);
            }
            if (lane == 0) { s_r0[warp] = sum; s_r1[warp] = ssq; }
            __syncthreads();
            if (tid < 8) {
                float s = s_r0[tid], q = s_r1[tid];
#pragma unroll
                for (int o = 4; o; o >>= 1) {
                    s += __shfl_xor_sync(0x000000ffu, s, o);
                    q += __shfl_xor_sync(0x000000ffu, q, o);
                }
                if (tid == 0) { s_mv[0] = s * (1.f / DH); s_mv[1] = q * (1.f / DH); }
            }
            __syncthreads();
            const float mu = s_mv[0];
            const float var = s_mv[1] - mu * mu;
            const float rstd = rsqrtf(var + 1e-5f);
#pragma unroll
            for (int u = 0; u < 2; u++) {
                const int d = tid + u * 256;
                const float h = (hr[u] - mu) * rstd * lnw[d] + lnb[d];
                g_z[b * 1024 + 512 + d] = h;
                g_hall[(size_t)(b * TT + t) * DH + d] = h;
            }
        }
        gsync(++bt);

        // ---- Phase E: hwh for next step (spread) ----
        hwh_phase();
        gsync(++bt);
    }
}

// ---------------- launch ----------------
extern "C" void kernel_launch(void* const* d_in, const int* in_sizes, int n_in,
                              void* d_out, int out_size)
{
    const float* patches = (const float*)d_in[0];
    const float* cls     = (const float*)d_in[1];
    const int*   tgt     = (const int*)  d_in[2];
    const float* emb     = (const float*)d_in[3];
    const float* kvW     = (const float*)d_in[4];
    const float* kvb     = (const float*)d_in[5];
    const float* ihW     = (const float*)d_in[6];
    const float* ihb     = (const float*)d_in[7];
    const float* icW     = (const float*)d_in[8];
    const float* icb     = (const float*)d_in[9];
    const float* aWh     = (const float*)d_in[10];
    const float* aWk     = (const float*)d_in[11];
    const float* av      = (const float*)d_in[12];
    const float* Wih     = (const float*)d_in[13];
    const float* Whh     = (const float*)d_in[14];
    const float* bih     = (const float*)d_in[15];
    const float* bhh     = (const float*)d_in[16];
    const float* lnw     = (const float*)d_in[17];
    const float* lnb     = (const float*)d_in[18];
    const float* outW    = (const float*)d_in[19];
    const float* outb    = (const float*)d_in[20];
    float* out = (float*)d_out;

    float *keys, *wk, *xseq, *Gx, *hall;
    unsigned* barp;
    cudaGetSymbolAddress((void**)&keys, g_keys);
    cudaGetSymbolAddress((void**)&wk,   g_wk);
    cudaGetSymbolAddress((void**)&xseq, g_xseq);
    cudaGetSymbolAddress((void**)&Gx,   g_Gx);
    cudaGetSymbolAddress((void**)&hall, g_hall);
    cudaGetSymbolAddress((void**)&barp, g_bar);

    // reset grid-barrier state (graph-capturable memset node)
    cudaMemsetAsync(barp, 0, 2 * sizeof(unsigned));

    // pre-loop
    gather_x<<<(BB * TT * DH) / 256, 256>>>(tgt, emb);
    gemm_nt<<<dim3(4, 49), 256>>>(patches, 768, kvW, 768, kvb, nullptr, keys, 512, BB * NN, 512, 768);
    gemm_nt<<<dim3(4, 49), 256>>>(keys, 512, aWk, 512, nullptr, nullptr, wk, 512, BB * NN, 512, 512);
    h0c0_kernel<<<GRID_P, 256>>>(cls, ihW, ihb, icW, icb);
    gemm_nt<<<dim3(16, 32), 256>>>(xseq, 512, Wih, 1024, bih, bhh, Gx, 2048, BB * TT, 2048, 512);

    // fused sequential decode loop (persistent, 4 grid barriers per step)
    decode_loop<<<GRID_P, 256>>>(aWh, av, Wih, Whh, lnw, lnb);

    // deferred logits: [4096, 10000] = hall @ outW^T + outb
    gemm_nt<<<dim3(79, 32), 256>>>(hall, 512, outW, 512, outb, nullptr, out, VV, BB * TT, VV, 512);
}

// round 6
// speedup vs baseline: 1.2364x; 1.1149x over previous
#include <cuda_runtime.h>
#include <cuda_bf16.h>
#include <math.h>

#define BB 32
#define NN 196
#define TT 128
#define DH 512
#define VV 10000
#define GRID_P 148
#define NH 18              // bankH rows/CTA: Whh(2048)+Wh(512)=2560 <= 148*18
#define NX 14              // bankX rows/CTA: Wih ctx cols 2048 <= 148*14
#define HSTR4 129          // float4 stride of h_s rows (516 floats, conflict-free)
#define DYN_FLOATS ((NH + NX) * 512 + 32 * 516)

// ---------------- device scratch (static, no allocation) ----------------
__device__ float g_keys[BB * NN * DH];
__device__ float g_wk  [BB * NN * DH];
__device__ float g_xseq[BB * TT * DH];
__device__ float g_Gx  [BB * TT * 4 * DH];
__device__ float g_hall[BB * TT * DH];
__device__ float g_h   [BB * DH];
__device__ float g_c   [BB * DH];
__device__ float g_hwh [BB * DH];        // b-major [b][512]
__device__ float g_gh  [BB * 4 * DH];    // h-part gates, b-major [b][2048]
__device__ float g_gx  [BB * 4 * DH];    // ctx-part gates, b-major
__device__ float g_ctx [BB * DH];
__device__ float g_ctxp[4][BB * DH];     // unnormalized chunk ctx
__device__ float g_cm[BB * 4], g_cs[BB * 4];
__device__ unsigned g_bar[2];            // [0]=count, [1]=generation
__device__ unsigned g_bcnt[BB * 32];     // padded per-b mini-barrier counters

__device__ __forceinline__ float fast_tanh(float x) {
    float y; asm("tanh.approx.f32 %0, %1;" : "=f"(y) : "f"(x)); return y;
}
__device__ __forceinline__ float sigm(float x) { return 1.f / (1.f + expf(-x)); }

// ---------------- generic SGEMM: C[M,N] = A[M,K] @ B[N,K]^T (+b1[n]+b2[n]) ----------------
__global__ __launch_bounds__(256) void gemm_nt(
    const float* __restrict__ A, int lda,
    const float* __restrict__ B, int ldb,
    const float* __restrict__ bias1, const float* __restrict__ bias2,
    float* __restrict__ C, int ldc, int M, int N, int K)
{
    __shared__ float As[8][128];
    __shared__ float Bs[8][128];
    const int tid = threadIdx.x;
    const int mBase = blockIdx.y * 128;
    const int nBase = blockIdx.x * 128;
    const int lr = tid >> 1;
    const int lc = (tid & 1) * 4;
    const int ty = tid >> 4;
    const int tx = tid & 15;

    float acc[8][8];
#pragma unroll
    for (int i = 0; i < 8; i++)
#pragma unroll
        for (int j = 0; j < 8; j++) acc[i][j] = 0.f;

    const bool aval = (mBase + lr) < M;
    const bool bval = (nBase + lr) < N;
    const float* Aptr = A + (size_t)(mBase + lr) * lda + lc;
    const float* Bptr = B + (size_t)(nBase + lr) * ldb + lc;

    for (int k0 = 0; k0 < K; k0 += 8) {
        float4 av = make_float4(0.f, 0.f, 0.f, 0.f);
        float4 bv = make_float4(0.f, 0.f, 0.f, 0.f);
        if (aval) av = *(const float4*)(Aptr + k0);
        if (bval) bv = *(const float4*)(Bptr + k0);
        As[lc + 0][lr] = av.x; As[lc + 1][lr] = av.y;
        As[lc + 2][lr] = av.z; As[lc + 3][lr] = av.w;
        Bs[lc + 0][lr] = bv.x; Bs[lc + 1][lr] = bv.y;
        Bs[lc + 2][lr] = bv.z; Bs[lc + 3][lr] = bv.w;
        __syncthreads();
#pragma unroll
        for (int kk = 0; kk < 8; kk++) {
            float a[8], b[8];
            *(float4*)&a[0] = *(const float4*)&As[kk][ty * 8];
            *(float4*)&a[4] = *(const float4*)&As[kk][ty * 8 + 4];
            *(float4*)&b[0] = *(const float4*)&Bs[kk][tx * 8];
            *(float4*)&b[4] = *(const float4*)&Bs[kk][tx * 8 + 4];
#pragma unroll
            for (int i = 0; i < 8; i++)
#pragma unroll
                for (int j = 0; j < 8; j++)
                    acc[i][j] = fmaf(a[i], b[j], acc[i][j]);
        }
        __syncthreads();
    }

#pragma unroll
    for (int i = 0; i < 8; i++) {
        const int gm = mBase + ty * 8 + i;
        if (gm >= M) continue;
#pragma unroll
        for (int j = 0; j < 8; j++) {
            const int gn = nBase + tx * 8 + j;
            if (gn < N) {
                float v = acc[i][j];
                if (bias1) v += bias1[gn];
                if (bias2) v += bias2[gn];
                C[(size_t)gm * ldc + gn] = v;
            }
        }
    }
}

// ---------------- embedding gather ----------------
__global__ void gather_x(const int* __restrict__ ids, const float* __restrict__ emb)
{
    const int i = blockIdx.x * 256 + threadIdx.x;
    if (i < BB * TT * DH) {
        const int d = i & (DH - 1);
        const int bt = i >> 9;
        g_xseq[i] = emb[(size_t)ids[bt] * DH + d];
    }
}

// ---------------- h0/c0: spread warp-per-dot ----------------
__global__ __launch_bounds__(256) void h0c0_kernel(
    const float* __restrict__ cls,
    const float* __restrict__ ihW, const float* __restrict__ ihb,
    const float* __restrict__ icW, const float* __restrict__ icb)
{
    const int gw = blockIdx.x * 8 + (threadIdx.x >> 5);
    const int lane = threadIdx.x & 31;
    for (int j = gw; j < 2 * BB * DH; j += GRID_P * 8) {
        const int sel = (j >= BB * DH);
        const int r = sel ? j - BB * DH : j;
        const int b = r >> 9, d = r & (DH - 1);
        const float4* W4 = (const float4*)((sel ? icW : ihW) + (size_t)d * 768);
        const float4* x4 = (const float4*)(cls + (size_t)b * 768);
        float acc = 0.f;
#pragma unroll
        for (int q = 0; q < 6; q++) {
            float4 w = W4[lane + 32 * q];
            float4 x = x4[lane + 32 * q];
            acc += w.x * x.x + w.y * x.y + w.z * x.z + w.w * x.w;
        }
#pragma unroll
        for (int o = 16; o; o >>= 1) acc += __shfl_xor_sync(0xffffffffu, acc, o);
        if (lane == 0) {
            if (sel) g_c[b * DH + d] = acc + icb[d];
            else     g_h[b * DH + d] = acc + ihb[d];
        }
    }
}

// ---------------- persistent decode loop ----------------
__global__ __launch_bounds__(256, 1) void decode_loop(
    const float* __restrict__ Wh, const float* __restrict__ av,
    const float* __restrict__ Wih, const float* __restrict__ Whh,
    const float* __restrict__ lnw, const float* __restrict__ lnb)
{
    extern __shared__ float smem[];
    float* wH = smem;                         // [NH][512]
    float* wX = smem + NH * 512;              // [NX][512]
    float4* hs4 = (float4*)(smem + (NH + NX) * 512);  // [32][HSTR4]

    __shared__ float s_v[512];
    __shared__ float s_hwh[512];
    __shared__ float s_sc[49];
    __shared__ float s_e[64];
    __shared__ float s_r0[8], s_r1[8], s_mv[2];

    const int tid = threadIdx.x;
    const int bid = blockIdx.x;
    const int warp = tid >> 5, lane = tid & 31;
    const int b32 = tid & 31, q = tid >> 5;   // for weight-phase mapping
    unsigned bt = 0;

    // ---- one-time: stage loop-invariant weights + v into smem ----
#pragma unroll
    for (int i = 0; i < NH; i++) {
        const int r = bid * NH + i;
        const float* src = (r < 2048) ? (Whh + (size_t)r * 512)
                          : (r < 2560) ? (Wh + (size_t)(r - 2048) * 512) : nullptr;
        if (src) for (int k = tid; k < 512; k += 256) wH[i * 512 + k] = src[k];
    }
#pragma unroll
    for (int i = 0; i < NX; i++) {
        const int r = bid * NX + i;
        if (r < 2048)
            for (int k = tid; k < 512; k += 256) wX[i * 512 + k] = Wih[(size_t)r * 1024 + 512 + k];
    }
    for (int k = tid; k < 512; k += 256) s_v[k] = av[k];

    auto gsync = [&](unsigned target) {
        __syncthreads();
        if (tid == 0) {
            __threadfence();
            unsigned a = atomicAdd(&g_bar[0], 1u);
            if (a == target * GRID_P - 1u) {
                atomicExch(&g_bar[1], target);
            } else {
                while (*(volatile unsigned*)&g_bar[1] < target) {}
            }
            __threadfence();
        }
        __syncthreads();
    };

    for (int t = 0; t < TT; t++) {
        // ======== Phase W: h-gates + hwh (weights in smem) ========
        {
            const float4* hsrc = (const float4*)g_h;
            for (int idx = tid; idx < 32 * 128; idx += 256)
                hs4[(idx >> 7) * HSTR4 + (idx & 127)] = hsrc[idx];
        }
        __syncthreads();
        {
            const float4* hp = hs4 + b32 * HSTR4;
            // rows i0=q, i1=q+8
            float4 a0 = make_float4(0.f, 0.f, 0.f, 0.f), a1 = a0;
            const float4* w0 = (const float4*)(wH + q * 512);
            const float4* w1 = (const float4*)(wH + (q + 8) * 512);
#pragma unroll 8
            for (int k = 0; k < 128; k++) {
                const float4 h = hp[k];
                const float4 x = w0[k];
                a0.x = fmaf(h.x, x.x, a0.x); a0.y = fmaf(h.y, x.y, a0.y);
                a0.z = fmaf(h.z, x.z, a0.z); a0.w = fmaf(h.w, x.w, a0.w);
                const float4 y = w1[k];
                a1.x = fmaf(h.x, y.x, a1.x); a1.y = fmaf(h.y, y.y, a1.y);
                a1.z = fmaf(h.z, y.z, a1.z); a1.w = fmaf(h.w, y.w, a1.w);
            }
            const float s0 = (a0.x + a0.y) + (a0.z + a0.w);
            const float s1 = (a1.x + a1.y) + (a1.z + a1.w);
            int r = bid * NH + q;
            if (r < 2048) g_gh[b32 * 2048 + r] = s0;
            else if (r < 2560) g_hwh[b32 * 512 + r - 2048] = s0;
            r = bid * NH + q + 8;
            if (r < 2048) g_gh[b32 * 2048 + r] = s1;
            else if (r < 2560) g_hwh[b32 * 512 + r - 2048] = s1;
            if (q < 2) {   // row i2=q+16
                float4 a2 = make_float4(0.f, 0.f, 0.f, 0.f);
                const float4* w2 = (const float4*)(wH + (q + 16) * 512);
#pragma unroll 8
                for (int k = 0; k < 128; k++) {
                    const float4 h = hp[k];
                    const float4 z = w2[k];
                    a2.x = fmaf(h.x, z.x, a2.x); a2.y = fmaf(h.y, z.y, a2.y);
                    a2.z = fmaf(h.z, z.z, a2.z); a2.w = fmaf(h.w, z.w, a2.w);
                }
                const float s2 = (a2.x + a2.y) + (a2.z + a2.w);
                r = bid * NH + q + 16;
                if (r < 2048) g_gh[b32 * 2048 + r] = s2;
                else if (r < 2560) g_hwh[b32 * 512 + r - 2048] = s2;
            }
        }
        gsync(++bt);

        // ======== Phase B: chunk scores + partial ctx + per-b combine ========
        if (bid < BB * 4) {
            const int b = bid >> 2, p = bid & 3;
            for (int k = tid; k < 512; k += 256) s_hwh[k] = g_hwh[b * 512 + k];
            __syncthreads();

            for (int n = warp; n < 49; n += 8) {
                const int ng = p * 49 + n;
                const float4* wk4 = (const float4*)(g_wk + ((size_t)(b * NN + ng)) * 512);
                const float4* hw4 = (const float4*)s_hwh;
                const float4* v4  = (const float4*)s_v;
                float s = 0.f;
#pragma unroll
                for (int i = 0; i < 4; i++) {
                    const float4 a = wk4[lane + 32 * i];
                    const float4 c = hw4[lane + 32 * i];
                    const float4 w = v4[lane + 32 * i];
                    s += fast_tanh(a.x + c.x) * w.x + fast_tanh(a.y + c.y) * w.y +
                         fast_tanh(a.z + c.z) * w.z + fast_tanh(a.w + c.w) * w.w;
                }
#pragma unroll
                for (int o = 16; o; o >>= 1) s += __shfl_xor_sync(0xffffffffu, s, o);
                if (lane == 0) s_sc[n] = s;
            }
            __syncthreads();

            if (warp == 0) {
                const float x0 = (lane < 49) ? s_sc[lane] : -1e30f;
                const float x1 = (lane + 32 < 49) ? s_sc[lane + 32] : -1e30f;
                float m = fmaxf(x0, x1);
#pragma unroll
                for (int o = 16; o; o >>= 1) m = fmaxf(m, __shfl_xor_sync(0xffffffffu, m, o));
                const float e0 = (lane < 49) ? __expf(x0 - m) : 0.f;
                const float e1 = (lane + 32 < 49) ? __expf(x1 - m) : 0.f;
                if (lane < 49) s_e[lane] = e0;
                if (lane + 32 < 49) s_e[lane + 32] = e1;
                float su = e0 + e1;
#pragma unroll
                for (int o = 16; o; o >>= 1) su += __shfl_xor_sync(0xffffffffu, su, o);
                if (lane == 0) { g_cm[b * 4 + p] = m; g_cs[b * 4 + p] = su; }
            }
            __syncthreads();

#pragma unroll
            for (int u = 0; u < 2; u++) {
                const int d = tid + 256 * u;
                const float* Kp = g_keys + ((size_t)(b * NN + p * 49)) * 512 + d;
                float a = 0.f;
#pragma unroll 7
                for (int i = 0; i < 49; i++) a = fmaf(s_e[i], Kp[(size_t)i * 512], a);
                g_ctxp[p][b * 512 + d] = a;
            }

            // mini-barrier among the 4 CTAs owning batch b
            __syncthreads();
            if (tid == 0) {
                __threadfence();
                atomicAdd(&g_bcnt[b * 32], 1u);
                while (*(volatile unsigned*)&g_bcnt[b * 32] < 4u * (unsigned)(t + 1)) {}
                __threadfence();
            }
            __syncthreads();

            if (tid < 128) {   // flash combine: this CTA owns d-slice [p*128, p*128+128)
                const int d = p * 128 + tid;
                const float m0 = g_cm[b*4+0], m1 = g_cm[b*4+1], m2 = g_cm[b*4+2], m3 = g_cm[b*4+3];
                const float m = fmaxf(fmaxf(m0, m1), fmaxf(m2, m3));
                const float e0 = __expf(m0 - m), e1 = __expf(m1 - m);
                const float e2 = __expf(m2 - m), e3 = __expf(m3 - m);
                const float den = e0 * g_cs[b*4+0] + e1 * g_cs[b*4+1] +
                                  e2 * g_cs[b*4+2] + e3 * g_cs[b*4+3];
                const float v = e0 * g_ctxp[0][b*512+d] + e1 * g_ctxp[1][b*512+d] +
                                e2 * g_ctxp[2][b*512+d] + e3 * g_ctxp[3][b*512+d];
                g_ctx[b * 512 + d] = v / den;
            }
        }
        gsync(++bt);

        // ======== Phase C: ctx-gates (weights in smem) ========
        {
            const float4* csrc = (const float4*)g_ctx;
            for (int idx = tid; idx < 32 * 128; idx += 256)
                hs4[(idx >> 7) * HSTR4 + (idx & 127)] = csrc[idx];
        }
        __syncthreads();
        {
            const float4* cp = hs4 + b32 * HSTR4;
            float4 a0 = make_float4(0.f, 0.f, 0.f, 0.f), a1 = a0;
            const float4* w0 = (const float4*)(wX + q * 512);
            const float4* w1 = (const float4*)(wX + ((q + 8 < NX) ? (q + 8) : 0) * 512);
#pragma unroll 8
            for (int k = 0; k < 128; k++) {
                const float4 h = cp[k];
                const float4 x = w0[k];
                a0.x = fmaf(h.x, x.x, a0.x); a0.y = fmaf(h.y, x.y, a0.y);
                a0.z = fmaf(h.z, x.z, a0.z); a0.w = fmaf(h.w, x.w, a0.w);
                const float4 y = w1[k];
                a1.x = fmaf(h.x, y.x, a1.x); a1.y = fmaf(h.y, y.y, a1.y);
                a1.z = fmaf(h.z, y.z, a1.z); a1.w = fmaf(h.w, y.w, a1.w);
            }
            const float s0 = (a0.x + a0.y) + (a0.z + a0.w);
            const float s1 = (a1.x + a1.y) + (a1.z + a1.w);
            int r = bid * NX + q;
            if (r < 2048) g_gx[b32 * 2048 + r] = s0;
            if (q + 8 < NX) {
                r = bid * NX + q + 8;
                if (r < 2048) g_gx[b32 * 2048 + r] = s1;
            }
        }
        gsync(++bt);

        // ======== Phase D: cell + LayerNorm (32 blocks) ========
        if (bid < BB) {
            const int b = bid;
            const float* Gx = g_Gx + ((size_t)(b * TT + t)) * 2048;
            const float* Gh = g_gh + (size_t)b * 2048;
            const float* Gc = g_gx + (size_t)b * 2048;
            float hr[2];
            float sum = 0.f, ssq = 0.f;
#pragma unroll
            for (int u = 0; u < 2; u++) {
                const int d = tid + 256 * u;
                const float gi = Gx[d]        + Gh[d]        + Gc[d];
                const float gf = Gx[512 + d]  + Gh[512 + d]  + Gc[512 + d];
                const float gg = Gx[1024 + d] + Gh[1024 + d] + Gc[1024 + d];
                const float go = Gx[1536 + d] + Gh[1536 + d] + Gc[1536 + d];
                const float c_old = g_c[b * DH + d];
                const float cn = sigm(gf) * c_old + sigm(gi) * tanhf(gg);
                g_c[b * DH + d] = cn;
                const float h = sigm(go) * tanhf(cn);
                hr[u] = h; sum += h; ssq += h * h;
            }
#pragma unroll
            for (int o = 16; o; o >>= 1) {
                sum += __shfl_xor_sync(0xffffffffu, sum, o);
                ssq += __shfl_xor_sync(0xffffffffu, ssq, o);
            }
            if (lane == 0) { s_r0[warp] = sum; s_r1[warp] = ssq; }
            __syncthreads();
            if (tid < 8) {
                float s = s_r0[tid], qq = s_r1[tid];
#pragma unroll
                for (int o = 4; o; o >>= 1) {
                    s += __shfl_xor_sync(0x000000ffu, s, o);
                    qq += __shfl_xor_sync(0x000000ffu, qq, o);
                }
                if (tid == 0) { s_mv[0] = s * (1.f / DH); s_mv[1] = qq * (1.f / DH); }
            }
            __syncthreads();
            const float mu = s_mv[0];
            const float var = s_mv[1] - mu * mu;
            const float rstd = rsqrtf(var + 1e-5f);
#pragma unroll
            for (int u = 0; u < 2; u++) {
                const int d = tid + 256 * u;
                const float h = (hr[u] - mu) * rstd * lnw[d] + lnb[d];
                g_h[b * DH + d] = h;
                g_hall[((size_t)(b * TT + t)) * DH + d] = h;
            }
        }
        gsync(++bt);
    }
}

// ---------------- launch ----------------
extern "C" void kernel_launch(void* const* d_in, const int* in_sizes, int n_in,
                              void* d_out, int out_size)
{
    const float* patches = (const float*)d_in[0];
    const float* cls     = (const float*)d_in[1];
    const int*   tgt     = (const int*)  d_in[2];
    const float* emb     = (const float*)d_in[3];
    const float* kvW     = (const float*)d_in[4];
    const float* kvb     = (const float*)d_in[5];
    const float* ihW     = (const float*)d_in[6];
    const float* ihb     = (const float*)d_in[7];
    const float* icW     = (const float*)d_in[8];
    const float* icb     = (const float*)d_in[9];
    const float* aWh     = (const float*)d_in[10];
    const float* aWk     = (const float*)d_in[11];
    const float* av      = (const float*)d_in[12];
    const float* Wih     = (const float*)d_in[13];
    const float* Whh     = (const float*)d_in[14];
    const float* bih     = (const float*)d_in[15];
    const float* bhh     = (const float*)d_in[16];
    const float* lnw     = (const float*)d_in[17];
    const float* lnb     = (const float*)d_in[18];
    const float* outW    = (const float*)d_in[19];
    const float* outb    = (const float*)d_in[20];
    float* out = (float*)d_out;

    float *keys, *wk, *xseq, *Gx, *hall;
    unsigned *barp, *bcntp;
    cudaGetSymbolAddress((void**)&keys, g_keys);
    cudaGetSymbolAddress((void**)&wk,   g_wk);
    cudaGetSymbolAddress((void**)&xseq, g_xseq);
    cudaGetSymbolAddress((void**)&Gx,   g_Gx);
    cudaGetSymbolAddress((void**)&hall, g_hall);
    cudaGetSymbolAddress((void**)&barp, g_bar);
    cudaGetSymbolAddress((void**)&bcntp, g_bcnt);

    // reset barrier state (graph-capturable memset nodes)
    cudaMemsetAsync(barp, 0, 2 * sizeof(unsigned));
    cudaMemsetAsync(bcntp, 0, BB * 32 * sizeof(unsigned));

    cudaFuncSetAttribute(decode_loop, cudaFuncAttributeMaxDynamicSharedMemorySize,
                         DYN_FLOATS * (int)sizeof(float));

    // pre-loop
    gather_x<<<(BB * TT * DH) / 256, 256>>>(tgt, emb);
    gemm_nt<<<dim3(4, 49), 256>>>(patches, 768, kvW, 768, kvb, nullptr, keys, 512, BB * NN, 512, 768);
    gemm_nt<<<dim3(4, 49), 256>>>(keys, 512, aWk, 512, nullptr, nullptr, wk, 512, BB * NN, 512, 512);
    h0c0_kernel<<<GRID_P, 256>>>(cls, ihW, ihb, icW, icb);
    gemm_nt<<<dim3(16, 32), 256>>>(xseq, 512, Wih, 1024, bih, bhh, Gx, 2048, BB * TT, 2048, 512);

    // fused sequential decode loop (persistent, smem-resident weights)
    decode_loop<<<GRID_P, 256, DYN_FLOATS * sizeof(float)>>>(aWh, av, Wih, Whh, lnw, lnb);

    // deferred logits: [4096, 10000] = hall @ outW^T + outb
    gemm_nt<<<dim3(79, 32), 256>>>(hall, 512, outW, 512, outb, nullptr, out, VV, BB * TT, VV, 512);
}

// round 9
// speedup vs baseline: 1.4047x; 1.1361x over previous
#include <cuda_runtime.h>
#include <cuda_bf16.h>
#include <math.h>
#include <stdint.h>

#define BB 32
#define NN 196
#define TT 128
#define DH 512
#define VV 10000
#define VPAD 10112
#define GRID_P 148
#define NH 18              // bankH rows/CTA: Whh(2048)+Wh(512)=2560 <= 148*18
#define NX 14              // bankX rows/CTA: Wih ctx cols 2048 <= 148*14
#define HSTR4 129          // float4 stride of h_s rows (516 floats, conflict-free)
#define DYN_FLOATS ((NH + NX) * 512 + 32 * 516)

// ---------------- device scratch (static, no allocation) ----------------
__device__ float g_keys[BB * NN * DH];
__device__ float g_wk  [BB * NN * DH];
__device__ float g_xseq[BB * TT * DH];
__device__ float g_Gx  [BB * TT * 4 * DH];
__device__ float g_h   [BB * DH];
__device__ float g_c   [BB * DH];
__device__ float g_hwh [BB * DH];
__device__ float g_gh  [BB * 4 * DH];
__device__ float g_gx  [BB * 4 * DH];
__device__ float g_ctx [BB * DH];
__device__ float g_ctxp[4][BB * DH];
__device__ float g_cm[BB * 4], g_cs[BB * 4];
__device__ unsigned g_sync[2 + BB * 32];     // [0]=count [1]=gen [2+b*32]=mini-barriers
__device__ __nv_bfloat16 g_hall_hi[BB * TT * DH];
__device__ __nv_bfloat16 g_hall_lo[BB * TT * DH];
__device__ __nv_bfloat16 g_w_hi[VPAD * DH];  // rows >= VV stay zero (module init)
__device__ __nv_bfloat16 g_w_lo[VPAD * DH];

__device__ __forceinline__ float fast_tanh(float x) {
    float y; asm("tanh.approx.f32 %0, %1;" : "=f"(y) : "f"(x)); return y;
}
__device__ __forceinline__ float sigm(float x) { return 1.f / (1.f + expf(-x)); }

// ---------------- mma.sync helpers (sm_80 PTX — valid at compute_103) ----------------
__device__ __forceinline__ uint32_t smem_u32(const void* p) {
    uint32_t a;
    asm("{ .reg .u64 t; cvta.to.shared.u64 t, %1; cvt.u32.u64 %0, t; }" : "=r"(a) : "l"(p));
    return a;
}
__device__ __forceinline__ void ldsm4(uint32_t* r, uint32_t addr) {
    asm volatile("ldmatrix.sync.aligned.m8n8.x4.shared.b16 {%0,%1,%2,%3}, [%4];"
        : "=r"(r[0]), "=r"(r[1]), "=r"(r[2]), "=r"(r[3]) : "r"(addr));
}
__device__ __forceinline__ void mma16816(float* c, const uint32_t* a, const uint32_t* b) {
    asm volatile("mma.sync.aligned.m16n8k16.row.col.f32.bf16.bf16.f32 "
        "{%0,%1,%2,%3}, {%4,%5,%6,%7}, {%8,%9}, {%0,%1,%2,%3};"
        : "+f"(c[0]), "+f"(c[1]), "+f"(c[2]), "+f"(c[3])
        : "r"(a[0]), "r"(a[1]), "r"(a[2]), "r"(a[3]), "r"(b[0]), "r"(b[1]));
}

// ---------------- generic SGEMM: C[M,N] = A[M,K] @ B[N,K]^T (+b1[n]+b2[n]) ----------------
__global__ __launch_bounds__(256) void gemm_nt(
    const float* __restrict__ A, int lda,
    const float* __restrict__ B, int ldb,
    const float* __restrict__ bias1, const float* __restrict__ bias2,
    float* __restrict__ C, int ldc, int M, int N, int K)
{
    __shared__ float As[8][128];
    __shared__ float Bs[8][128];
    const int tid = threadIdx.x;
    const int mBase = blockIdx.y * 128;
    const int nBase = blockIdx.x * 128;
    const int lr = tid >> 1;
    const int lc = (tid & 1) * 4;
    const int ty = tid >> 4;
    const int tx = tid & 15;

    float acc[8][8];
#pragma unroll
    for (int i = 0; i < 8; i++)
#pragma unroll
        for (int j = 0; j < 8; j++) acc[i][j] = 0.f;

    const bool aval = (mBase + lr) < M;
    const bool bval = (nBase + lr) < N;
    const float* Aptr = A + (size_t)(mBase + lr) * lda + lc;
    const float* Bptr = B + (size_t)(nBase + lr) * ldb + lc;

    for (int k0 = 0; k0 < K; k0 += 8) {
        float4 av = make_float4(0.f, 0.f, 0.f, 0.f);
        float4 bv = make_float4(0.f, 0.f, 0.f, 0.f);
        if (aval) av = *(const float4*)(Aptr + k0);
        if (bval) bv = *(const float4*)(Bptr + k0);
        As[lc + 0][lr] = av.x; As[lc + 1][lr] = av.y;
        As[lc + 2][lr] = av.z; As[lc + 3][lr] = av.w;
        Bs[lc + 0][lr] = bv.x; Bs[lc + 1][lr] = bv.y;
        Bs[lc + 2][lr] = bv.z; Bs[lc + 3][lr] = bv.w;
        __syncthreads();
#pragma unroll
        for (int kk = 0; kk < 8; kk++) {
            float a[8], b[8];
            *(float4*)&a[0] = *(const float4*)&As[kk][ty * 8];
            *(float4*)&a[4] = *(const float4*)&As[kk][ty * 8 + 4];
            *(float4*)&b[0] = *(const float4*)&Bs[kk][tx * 8];
            *(float4*)&b[4] = *(const float4*)&Bs[kk][tx * 8 + 4];
#pragma unroll
            for (int i = 0; i < 8; i++)
#pragma unroll
                for (int j = 0; j < 8; j++)
                    acc[i][j] = fmaf(a[i], b[j], acc[i][j]);
        }
        __syncthreads();
    }

#pragma unroll
    for (int i = 0; i < 8; i++) {
        const int gm = mBase + ty * 8 + i;
        if (gm >= M) continue;
#pragma unroll
        for (int j = 0; j < 8; j++) {
            const int gn = nBase + tx * 8 + j;
            if (gn < N) {
                float v = acc[i][j];
                if (bias1) v += bias1[gn];
                if (bias2) v += bias2[gn];
                C[(size_t)gm * ldc + gn] = v;
            }
        }
    }
}

// ---------------- gather + outW bf16 split conversion ----------------
__global__ void gather_conv(const int* __restrict__ ids, const float* __restrict__ emb,
                            const float* __restrict__ outW)
{
    if (blockIdx.x < 8192) {
        const int i = blockIdx.x * 256 + threadIdx.x;
        const int d = i & (DH - 1);
        const int bt = i >> 9;
        g_xseq[i] = emb[(size_t)ids[bt] * DH + d];
    } else {
        const int j = (blockIdx.x - 8192) * 256 + threadIdx.x;
        if (j < VV * DH) {
            const float w = outW[j];
            const __nv_bfloat16 hi = __float2bfloat16(w);
            g_w_hi[j] = hi;
            g_w_lo[j] = __float2bfloat16(w - __bfloat162float(hi));
        }
    }
}

// ---------------- persistent decode loop ----------------
__global__ __launch_bounds__(256, 1) void decode_loop(
    const float* __restrict__ Wh, const float* __restrict__ av,
    const float* __restrict__ Wih, const float* __restrict__ Whh,
    const float* __restrict__ lnw, const float* __restrict__ lnb,
    const float* __restrict__ cls,
    const float* __restrict__ ihW, const float* __restrict__ ihb,
    const float* __restrict__ icW, const float* __restrict__ icb)
{
    extern __shared__ float smem[];
    float* wH = smem;                                  // [NH][512]
    float* wX = smem + NH * 512;                       // [NX][512]
    float4* hs4 = (float4*)(smem + (NH + NX) * 512);   // [32][HSTR4]

    __shared__ float s_v[512];
    __shared__ float s_hwh[512];
    __shared__ float s_sc[49];
    __shared__ float s_e[64];
    __shared__ float s_r0[8], s_r1[8], s_mv[2];

    const int tid = threadIdx.x;
    const int bid = blockIdx.x;
    const int warp = tid >> 5, lane = tid & 31;
    const int gwarp = bid * 8 + warp;
    const int b32 = tid & 31, q = tid >> 5;
    unsigned bt = 0;

    // ---- stage loop-invariant weights + v into smem ----
#pragma unroll
    for (int i = 0; i < NH; i++) {
        const int r = bid * NH + i;
        const float* src = (r < 2048) ? (Whh + (size_t)r * 512)
                          : (r < 2560) ? (Wh + (size_t)(r - 2048) * 512) : nullptr;
        if (src) for (int k = tid; k < 512; k += 256) wH[i * 512 + k] = src[k];
    }
#pragma unroll
    for (int i = 0; i < NX; i++) {
        const int r = bid * NX + i;
        if (r < 2048)
            for (int k = tid; k < 512; k += 256) wX[i * 512 + k] = Wih[(size_t)r * 1024 + 512 + k];
    }
    for (int k = tid; k < 512; k += 256) s_v[k] = av[k];

    auto gsync = [&](unsigned target) {
        __syncthreads();
        if (tid == 0) {
            __threadfence();
            unsigned a = atomicAdd(&g_sync[0], 1u);
            if (a == target * GRID_P - 1u) {
                atomicExch(&g_sync[1], target);
            } else {
                while (*(volatile unsigned*)&g_sync[1] < target) {}
            }
            __threadfence();
        }
        __syncthreads();
    };

    // ---- h0/c0 (folded) ----
    for (int j = gwarp; j < 2 * BB * DH; j += GRID_P * 8) {
        const int sel = (j >= BB * DH);
        const int r = sel ? j - BB * DH : j;
        const int b = r >> 9, d = r & (DH - 1);
        const float4* W4 = (const float4*)((sel ? icW : ihW) + (size_t)d * 768);
        const float4* x4 = (const float4*)(cls + (size_t)b * 768);
        float acc = 0.f;
#pragma unroll
        for (int p = 0; p < 6; p++) {
            float4 w = W4[lane + 32 * p];
            float4 x = x4[lane + 32 * p];
            acc += w.x * x.x + w.y * x.y + w.z * x.z + w.w * x.w;
        }
#pragma unroll
        for (int o = 16; o; o >>= 1) acc += __shfl_xor_sync(0xffffffffu, acc, o);
        if (lane == 0) {
            if (sel) g_c[b * DH + d] = acc + icb[d];
            else     g_h[b * DH + d] = acc + ihb[d];
        }
    }
    gsync(++bt);

    for (int t = 0; t < TT; t++) {
        // ======== Phase W: h-gates + hwh (weights in smem) ========
        {
            const float4* hsrc = (const float4*)g_h;
            for (int idx = tid; idx < 32 * 128; idx += 256)
                hs4[(idx >> 7) * HSTR4 + (idx & 127)] = hsrc[idx];
        }
        __syncthreads();
        {
            const float4* hp = hs4 + b32 * HSTR4;
            float4 a0 = make_float4(0.f, 0.f, 0.f, 0.f), a1 = a0, a2 = a0;
            const float4* w0 = (const float4*)(wH + q * 512);
            const float4* w1 = (const float4*)(wH + (q + 8) * 512);
            const float4* w2 = (const float4*)(wH + ((q < 2) ? (q + 16) : 0) * 512);
#pragma unroll 8
            for (int k = 0; k < 128; k++) {
                const float4 h = hp[k];
                const float4 x = w0[k];
                a0.x = fmaf(h.x, x.x, a0.x); a0.y = fmaf(h.y, x.y, a0.y);
                a0.z = fmaf(h.z, x.z, a0.z); a0.w = fmaf(h.w, x.w, a0.w);
                const float4 y = w1[k];
                a1.x = fmaf(h.x, y.x, a1.x); a1.y = fmaf(h.y, y.y, a1.y);
                a1.z = fmaf(h.z, y.z, a1.z); a1.w = fmaf(h.w, y.w, a1.w);
                const float4 z = w2[k];
                a2.x = fmaf(h.x, z.x, a2.x); a2.y = fmaf(h.y, z.y, a2.y);
                a2.z = fmaf(h.z, z.z, a2.z); a2.w = fmaf(h.w, z.w, a2.w);
            }
            const float s0 = (a0.x + a0.y) + (a0.z + a0.w);
            const float s1 = (a1.x + a1.y) + (a1.z + a1.w);
            const float s2 = (a2.x + a2.y) + (a2.z + a2.w);
            int r = bid * NH + q;
            if (r < 2048) g_gh[b32 * 2048 + r] = s0;
            else if (r < 2560) g_hwh[b32 * 512 + r - 2048] = s0;
            r = bid * NH + q + 8;
            if (r < 2048) g_gh[b32 * 2048 + r] = s1;
            else if (r < 2560) g_hwh[b32 * 512 + r - 2048] = s1;
            if (q < 2) {
                r = bid * NH + q + 16;
                if (r < 2048) g_gh[b32 * 2048 + r] = s2;
                else if (r < 2560) g_hwh[b32 * 512 + r - 2048] = s2;
            }
        }
        gsync(++bt);

        // ======== Phase B: chunk scores + partial ctx + per-b combine ========
        if (bid < BB * 4) {
            const int b = bid >> 2, p = bid & 3;
            for (int k = tid; k < 512; k += 256) s_hwh[k] = g_hwh[b * 512 + k];
            __syncthreads();

            for (int n = warp; n < 49; n += 8) {
                const int ng = p * 49 + n;
                const float4* wk4 = (const float4*)(g_wk + ((size_t)(b * NN + ng)) * 512);
                const float4* hw4 = (const float4*)s_hwh;
                const float4* v4  = (const float4*)s_v;
                float s = 0.f;
#pragma unroll
                for (int i = 0; i < 4; i++) {
                    const float4 a = wk4[lane + 32 * i];
                    const float4 c = hw4[lane + 32 * i];
                    const float4 w = v4[lane + 32 * i];
                    s += fast_tanh(a.x + c.x) * w.x + fast_tanh(a.y + c.y) * w.y +
                         fast_tanh(a.z + c.z) * w.z + fast_tanh(a.w + c.w) * w.w;
                }
#pragma unroll
                for (int o = 16; o; o >>= 1) s += __shfl_xor_sync(0xffffffffu, s, o);
                if (lane == 0) s_sc[n] = s;
            }
            __syncthreads();

            if (warp == 0) {
                const float x0 = (lane < 49) ? s_sc[lane] : -1e30f;
                const float x1 = (lane + 32 < 49) ? s_sc[lane + 32] : -1e30f;
                float m = fmaxf(x0, x1);
#pragma unroll
                for (int o = 16; o; o >>= 1) m = fmaxf(m, __shfl_xor_sync(0xffffffffu, m, o));
                const float e0 = (lane < 49) ? __expf(x0 - m) : 0.f;
                const float e1 = (lane + 32 < 49) ? __expf(x1 - m) : 0.f;
                if (lane < 49) s_e[lane] = e0;
                if (lane + 32 < 49) s_e[lane + 32] = e1;
                float su = e0 + e1;
#pragma unroll
                for (int o = 16; o; o >>= 1) su += __shfl_xor_sync(0xffffffffu, su, o);
                if (lane == 0) { g_cm[b * 4 + p] = m; g_cs[b * 4 + p] = su; }
            }
            __syncthreads();

#pragma unroll
            for (int u = 0; u < 2; u++) {
                const int d = tid + 256 * u;
                const float* Kp = g_keys + ((size_t)(b * NN + p * 49)) * 512 + d;
                float a = 0.f;
#pragma unroll 7
                for (int i = 0; i < 49; i++) a = fmaf(s_e[i], Kp[(size_t)i * 512], a);
                g_ctxp[p][b * 512 + d] = a;
            }

            __syncthreads();
            if (tid == 0) {
                __threadfence();
                atomicAdd(&g_sync[2 + b * 32], 1u);
                while (*(volatile unsigned*)&g_sync[2 + b * 32] < 4u * (unsigned)(t + 1)) {}
                __threadfence();
            }
            __syncthreads();

            if (tid < 128) {
                const int d = p * 128 + tid;
                const float m0 = g_cm[b*4+0], m1 = g_cm[b*4+1], m2 = g_cm[b*4+2], m3 = g_cm[b*4+3];
                const float m = fmaxf(fmaxf(m0, m1), fmaxf(m2, m3));
                const float e0 = __expf(m0 - m), e1 = __expf(m1 - m);
                const float e2 = __expf(m2 - m), e3 = __expf(m3 - m);
                const float den = e0 * g_cs[b*4+0] + e1 * g_cs[b*4+1] +
                                  e2 * g_cs[b*4+2] + e3 * g_cs[b*4+3];
                const float v = e0 * g_ctxp[0][b*512+d] + e1 * g_ctxp[1][b*512+d] +
                                e2 * g_ctxp[2][b*512+d] + e3 * g_ctxp[3][b*512+d];
                g_ctx[b * 512 + d] = v / den;
            }
        }
        gsync(++bt);

        // ======== Phase C: ctx-gates (weights in smem) ========
        {
            const float4* csrc = (const float4*)g_ctx;
            for (int idx = tid; idx < 32 * 128; idx += 256)
                hs4[(idx >> 7) * HSTR4 + (idx & 127)] = csrc[idx];
        }
        __syncthreads();
        {
            const float4* cp = hs4 + b32 * HSTR4;
            float4 a0 = make_float4(0.f, 0.f, 0.f, 0.f), a1 = a0;
            const float4* w0 = (const float4*)(wX + q * 512);
            const float4* w1 = (const float4*)(wX + ((q + 8 < NX) ? (q + 8) : 0) * 512);
#pragma unroll 8
            for (int k = 0; k < 128; k++) {
                const float4 h = cp[k];
                const float4 x = w0[k];
                a0.x = fmaf(h.x, x.x, a0.x); a0.y = fmaf(h.y, x.y, a0.y);
                a0.z = fmaf(h.z, x.z, a0.z); a0.w = fmaf(h.w, x.w, a0.w);
                const float4 y = w1[k];
                a1.x = fmaf(h.x, y.x, a1.x); a1.y = fmaf(h.y, y.y, a1.y);
                a1.z = fmaf(h.z, y.z, a1.z); a1.w = fmaf(h.w, y.w, a1.w);
            }
            const float s0 = (a0.x + a0.y) + (a0.z + a0.w);
            const float s1 = (a1.x + a1.y) + (a1.z + a1.w);
            int r = bid * NX + q;
            if (r < 2048) g_gx[b32 * 2048 + r] = s0;
            if (q + 8 < NX) {
                r = bid * NX + q + 8;
                if (r < 2048) g_gx[b32 * 2048 + r] = s1;
            }
        }
        gsync(++bt);

        // ======== Phase D: cell + LayerNorm (32 blocks) ========
        if (bid < BB) {
            const int b = bid;
            const float* Gx = g_Gx + ((size_t)(b * TT + t)) * 2048;
            const float* Gh = g_gh + (size_t)b * 2048;
            const float* Gc = g_gx + (size_t)b * 2048;
            float hr[2];
            float sum = 0.f, ssq = 0.f;
#pragma unroll
            for (int u = 0; u < 2; u++) {
                const int d = tid + 256 * u;
                const float gi = Gx[d]        + Gh[d]        + Gc[d];
                const float gf = Gx[512 + d]  + Gh[512 + d]  + Gc[512 + d];
                const float gg = Gx[1024 + d] + Gh[1024 + d] + Gc[1024 + d];
                const float go = Gx[1536 + d] + Gh[1536 + d] + Gc[1536 + d];
                const float c_old = g_c[b * DH + d];
                const float cn = sigm(gf) * c_old + sigm(gi) * tanhf(gg);
                g_c[b * DH + d] = cn;
                const float h = sigm(go) * tanhf(cn);
                hr[u] = h; sum += h; ssq += h * h;
            }
#pragma unroll
            for (int o = 16; o; o >>= 1) {
                sum += __shfl_xor_sync(0xffffffffu, sum, o);
                ssq += __shfl_xor_sync(0xffffffffu, ssq, o);
            }
            if (lane == 0) { s_r0[warp] = sum; s_r1[warp] = ssq; }
            __syncthreads();
            if (tid < 8) {
                float s = s_r0[tid], qq = s_r1[tid];
#pragma unroll
                for (int o = 4; o; o >>= 1) {
                    s += __shfl_xor_sync(0x000000ffu, s, o);
                    qq += __shfl_xor_sync(0x000000ffu, qq, o);
                }
                if (tid == 0) { s_mv[0] = s * (1.f / DH); s_mv[1] = qq * (1.f / DH); }
            }
            __syncthreads();
            const float mu = s_mv[0];
            const float var = s_mv[1] - mu * mu;
            const float rstd = rsqrtf(var + 1e-5f);
#pragma unroll
            for (int u = 0; u < 2; u++) {
                const int d = tid + 256 * u;
                const float h = (hr[u] - mu) * rstd * lnw[d] + lnb[d];
                g_h[b * DH + d] = h;
                const size_t idx = ((size_t)(b * TT + t)) * DH + d;
                const __nv_bfloat16 hi = __float2bfloat16(h);
                g_hall_hi[idx] = hi;
                g_hall_lo[idx] = __float2bfloat16(h - __bfloat162float(hi));
            }
        }
        gsync(++bt);
    }
}

// ---------------- logits: mma.sync split-bf16, C[4096,10000] = hall @ outW^T + b ----------------
// CTA 128x128, K=512 in SIXTEEN chunks of 32. smem tiles padded to 40-bf16 row stride.
#define LSTR 40
__global__ __launch_bounds__(256) void logits_mma(float* __restrict__ out,
                                                  const float* __restrict__ outb)
{
    __shared__ __nv_bfloat16 sAh[128 * LSTR], sAl[128 * LSTR];
    __shared__ __nv_bfloat16 sBh[128 * LSTR], sBl[128 * LSTR];

    const int tid = threadIdx.x;
    const int wid = tid >> 5, lane = tid & 31;
    const int nBase = blockIdx.x * 128;
    const int mBase = blockIdx.y * 128;
    const int wm = (wid & 3) * 32;     // warp m-offset (4 warps x 32 rows)
    const int wn = (wid >> 2) * 64;    // warp n-offset (2 warps x 64 cols)

    const uint32_t uAh = smem_u32(sAh), uAl = smem_u32(sAl);
    const uint32_t uBh = smem_u32(sBh), uBl = smem_u32(sBl);

    float acc[2][8][4];
#pragma unroll
    for (int i = 0; i < 2; i++)
#pragma unroll
        for (int j = 0; j < 8; j++)
#pragma unroll
            for (int k = 0; k < 4; k++) acc[i][j][k] = 0.f;

    // copy indices: thread covers 2 consecutive 16B segs of one row per matrix
    const int cr = tid >> 1;             // row 0..127
    const int cs = (tid & 1) * 2;        // seg 0 or 2 (of 4 segs x 16B = 64B/row)

    for (int ch = 0; ch < 16; ch++) {    // 16 chunks x 32 = K=512 (R8 bug: was 8)
        {
            const size_t goff = (size_t)ch * 32 + cs * 8;
            const uint4* pAh = (const uint4*)(g_hall_hi + (size_t)(mBase + cr) * 512 + goff);
            const uint4* pAl = (const uint4*)(g_hall_lo + (size_t)(mBase + cr) * 512 + goff);
            const uint4* pBh = (const uint4*)(g_w_hi + (size_t)(nBase + cr) * 512 + goff);
            const uint4* pBl = (const uint4*)(g_w_lo + (size_t)(nBase + cr) * 512 + goff);
            uint4* dAh = (uint4*)(sAh + cr * LSTR + cs * 8);
            uint4* dAl = (uint4*)(sAl + cr * LSTR + cs * 8);
            uint4* dBh = (uint4*)(sBh + cr * LSTR + cs * 8);
            uint4* dBl = (uint4*)(sBl + cr * LSTR + cs * 8);
            dAh[0] = pAh[0]; dAh[1] = pAh[1];
            dAl[0] = pAl[0]; dAl[1] = pAl[1];
            dBh[0] = pBh[0]; dBh[1] = pBh[1];
            dBl[0] = pBl[0]; dBl[1] = pBl[1];
        }
        __syncthreads();

#pragma unroll
        for (int ks = 0; ks < 2; ks++) {
            uint32_t ah[2][4], al[2][4], bh[8][2], bl[8][2];
            // A frags: 2 m16 tiles
#pragma unroll
            for (int mt = 0; mt < 2; mt++) {
                const uint32_t off =
                    ((wm + mt * 16 + (lane & 15)) * LSTR + ks * 16 + (lane >> 4) * 8) * 2;
                ldsm4(ah[mt], uAh + off);
                ldsm4(al[mt], uAl + off);
            }
            // B frags: 8 n8 tiles via 4 x4-loads (2 tiles each)
#pragma unroll
            for (int p = 0; p < 4; p++) {
                const uint32_t off =
                    ((wn + p * 16 + ((lane >> 4) & 1) * 8 + (lane & 7)) * LSTR +
                     ks * 16 + ((lane >> 3) & 1) * 8) * 2;
                uint32_t r4[4];
                ldsm4(r4, uBh + off);
                bh[2 * p][0] = r4[0]; bh[2 * p][1] = r4[1];
                bh[2 * p + 1][0] = r4[2]; bh[2 * p + 1][1] = r4[3];
                ldsm4(r4, uBl + off);
                bl[2 * p][0] = r4[0]; bl[2 * p][1] = r4[1];
                bl[2 * p + 1][0] = r4[2]; bl[2 * p + 1][1] = r4[3];
            }
#pragma unroll
            for (int mt = 0; mt < 2; mt++)
#pragma unroll
                for (int nt = 0; nt < 8; nt++) {
                    mma16816(acc[mt][nt], ah[mt], bh[nt]);
                    mma16816(acc[mt][nt], ah[mt], bl[nt]);
                    mma16816(acc[mt][nt], al[mt], bh[nt]);
                }
        }
        __syncthreads();
    }

    // epilogue: c-frag rows = lane>>2 (+8), cols = 2*(lane&3)+{0,1}
    const int erow = lane >> 2;
    const int ecol = (lane & 3) * 2;
#pragma unroll
    for (int mt = 0; mt < 2; mt++) {
#pragma unroll
        for (int nt = 0; nt < 8; nt++) {
            const int gn = nBase + wn + nt * 8 + ecol;
            if (gn < VV) {
                const float b0 = outb[gn], b1 = outb[gn + 1];
                const int r0 = mBase + wm + mt * 16 + erow;
                float2 v0 = make_float2(acc[mt][nt][0] + b0, acc[mt][nt][1] + b1);
                float2 v1 = make_float2(acc[mt][nt][2] + b0, acc[mt][nt][3] + b1);
                *(float2*)&out[(size_t)r0 * VV + gn] = v0;
                *(float2*)&out[(size_t)(r0 + 8) * VV + gn] = v1;
            }
        }
    }
}

// ---------------- launch ----------------
extern "C" void kernel_launch(void* const* d_in, const int* in_sizes, int n_in,
                              void* d_out, int out_size)
{
    const float* patches = (const float*)d_in[0];
    const float* cls     = (const float*)d_in[1];
    const int*   tgt     = (const int*)  d_in[2];
    const float* emb     = (const float*)d_in[3];
    const float* kvW     = (const float*)d_in[4];
    const float* kvb     = (const float*)d_in[5];
    const float* ihW     = (const float*)d_in[6];
    const float* ihb     = (const float*)d_in[7];
    const float* icW     = (const float*)d_in[8];
    const float* icb     = (const float*)d_in[9];
    const float* aWh     = (const float*)d_in[10];
    const float* aWk     = (const float*)d_in[11];
    const float* av      = (const float*)d_in[12];
    const float* Wih     = (const float*)d_in[13];
    const float* Whh     = (const float*)d_in[14];
    const float* bih     = (const float*)d_in[15];
    const float* bhh     = (const float*)d_in[16];
    const float* lnw     = (const float*)d_in[17];
    const float* lnb     = (const float*)d_in[18];
    const float* outW    = (const float*)d_in[19];
    const float* outb    = (const float*)d_in[20];
    float* out = (float*)d_out;

    float *keys, *wk, *xseq, *Gx;
    unsigned* syncp;
    cudaGetSymbolAddress((void**)&keys, g_keys);
    cudaGetSymbolAddress((void**)&wk,   g_wk);
    cudaGetSymbolAddress((void**)&xseq, g_xseq);
    cudaGetSymbolAddress((void**)&Gx,   g_Gx);
    cudaGetSymbolAddress((void**)&syncp, g_sync);

    cudaMemsetAsync(syncp, 0, (2 + BB * 32) * sizeof(unsigned));

    cudaFuncSetAttribute(decode_loop, cudaFuncAttributeMaxDynamicSharedMemorySize,
                         DYN_FLOATS * (int)sizeof(float));

    gather_conv<<<8192 + 20000, 256>>>(tgt, emb, outW);
    gemm_nt<<<dim3(4, 49), 256>>>(patches, 768, kvW, 768, kvb, nullptr, keys, 512, BB * NN, 512, 768);
    gemm_nt<<<dim3(4, 49), 256>>>(keys, 512, aWk, 512, nullptr, nullptr, wk, 512, BB * NN, 512, 512);
    gemm_nt<<<dim3(16, 32), 256>>>(xseq, 512, Wih, 1024, bih, bhh, Gx, 2048, BB * TT, 2048, 512);

    decode_loop<<<GRID_P, 256, DYN_FLOATS * sizeof(float)>>>(
        aWh, av, Wih, Whh, lnw, lnb, cls, ihW, ihb, icW, icb);

    logits_mma<<<dim3(79, 32), 256>>>(out, outb);
}

// round 10
// speedup vs baseline: 1.4619x; 1.0407x over previous
#include <cuda_runtime.h>
#include <cuda_bf16.h>
#include <math.h>
#include <stdint.h>

#define BB 32
#define NN 196
#define TT 128
#define DH 512
#define VV 10000
#define VPAD 10112
#define GRID_P 148
#define NH 18              // bankH rows/CTA: Whh(2048)+Wh(512)=2560 <= 148*18
#define NX 14              // bankX rows/CTA: Wih ctx cols 2048 <= 148*14
#define HSTR4 129          // float4 stride of h_s rows (516 floats, conflict-free)
#define DYN_FLOATS ((NH + NX) * 512 + 32 * 516)

typedef __nv_bfloat16 bf16;

// ---------------- device scratch (static, no allocation) ----------------
__device__ float g_keys[BB * NN * DH];
__device__ float g_wk  [BB * NN * DH];
__device__ float g_Gx  [BB * TT * 4 * DH];
__device__ float g_h   [BB * DH];
__device__ float g_c   [BB * DH];
__device__ float g_hwh [BB * DH];
__device__ float g_gh  [BB * 4 * DH];
__device__ float g_gx  [BB * 4 * DH];
__device__ float g_ctx [BB * DH];
__device__ float g_ctxp[4][BB * DH];
__device__ float g_cm[BB * 4], g_cs[BB * 4];
__device__ unsigned g_sync[2 + BB * 32];     // [0]=count [1]=gen [2+b*32]=mini-barriers
__device__ bf16 g_hall_hi[BB * TT * DH], g_hall_lo[BB * TT * DH];
__device__ bf16 g_w_hi[VPAD * DH], g_w_lo[VPAD * DH];   // rows >= VV stay zero
__device__ bf16 g_x_hi[BB * TT * DH], g_x_lo[BB * TT * DH];
__device__ bf16 g_p_hi[BB * NN * 768], g_p_lo[BB * NN * 768];
__device__ bf16 g_kvw_hi[512 * 768], g_kvw_lo[512 * 768];
__device__ bf16 g_awk_hi[512 * 512], g_awk_lo[512 * 512];
__device__ bf16 g_wih_hi[2048 * 512], g_wih_lo[2048 * 512];
__device__ bf16 g_keys_hi[BB * NN * DH], g_keys_lo[BB * NN * DH];

__device__ __forceinline__ float fast_tanh(float x) {
    float y; asm("tanh.approx.f32 %0, %1;" : "=f"(y) : "f"(x)); return y;
}
__device__ __forceinline__ float sigm(float x) { return 1.f / (1.f + expf(-x)); }
__device__ __forceinline__ void split_bf16(float v, bf16* hi, bf16* lo) {
    const bf16 h = __float2bfloat16(v);
    *hi = h;
    *lo = __float2bfloat16(v - __bfloat162float(h));
}

// ---------------- mma.sync helpers (sm_80 PTX — valid at compute_103) ----------------
__device__ __forceinline__ uint32_t smem_u32(const void* p) {
    uint32_t a;
    asm("{ .reg .u64 t; cvta.to.shared.u64 t, %1; cvt.u32.u64 %0, t; }" : "=r"(a) : "l"(p));
    return a;
}
__device__ __forceinline__ void ldsm4(uint32_t* r, uint32_t addr) {
    asm volatile("ldmatrix.sync.aligned.m8n8.x4.shared.b16 {%0,%1,%2,%3}, [%4];"
        : "=r"(r[0]), "=r"(r[1]), "=r"(r[2]), "=r"(r[3]) : "r"(addr));
}
__device__ __forceinline__ void mma16816(float* c, const uint32_t* a, const uint32_t* b) {
    asm volatile("mma.sync.aligned.m16n8k16.row.col.f32.bf16.bf16.f32 "
        "{%0,%1,%2,%3}, {%4,%5,%6,%7}, {%8,%9}, {%0,%1,%2,%3};"
        : "+f"(c[0]), "+f"(c[1]), "+f"(c[2]), "+f"(c[3])
        : "r"(a[0]), "r"(a[1]), "r"(a[2]), "r"(a[3]), "r"(b[0]), "r"(b[1]));
}

// ---------------- generic split-bf16 MMA GEMM: C[M,N] = A@B^T (+b1+b2) ----------------
// CTA tile 128x128, K = kChunks*32. A rows ldA elems, B rows ldB elems.
// Optional fp32 out C (cols < nLimit) and optional bf16 hi/lo out (for chaining).
#define LSTR 40
__global__ __launch_bounds__(256) void mma_nt(
    const bf16* __restrict__ Ah, const bf16* __restrict__ Al,
    const bf16* __restrict__ Bh, const bf16* __restrict__ Bl,
    const float* __restrict__ bias1, const float* __restrict__ bias2,
    float* __restrict__ C, int ldc, int nLimit, int kChunks, int ldA, int ldB,
    bf16* __restrict__ Chi, bf16* __restrict__ Clo)
{
    __shared__ bf16 sAh[128 * LSTR], sAl[128 * LSTR];
    __shared__ bf16 sBh[128 * LSTR], sBl[128 * LSTR];

    const int tid = threadIdx.x;
    const int wid = tid >> 5, lane = tid & 31;
    const int nBase = blockIdx.x * 128;
    const int mBase = blockIdx.y * 128;
    const int wm = (wid & 3) * 32;     // 4 warps x 32 rows
    const int wn = (wid >> 2) * 64;    // 2 warps x 64 cols

    const uint32_t uAh = smem_u32(sAh), uAl = smem_u32(sAl);
    const uint32_t uBh = smem_u32(sBh), uBl = smem_u32(sBl);

    float acc[2][8][4];
#pragma unroll
    for (int i = 0; i < 2; i++)
#pragma unroll
        for (int j = 0; j < 8; j++)
#pragma unroll
            for (int k = 0; k < 4; k++) acc[i][j][k] = 0.f;

    const int cr = tid >> 1;             // row 0..127
    const int cs = (tid & 1) * 2;        // seg 0 or 2

    for (int ch = 0; ch < kChunks; ch++) {
        {
            const int goff = ch * 32 + cs * 8;
            const uint4* pAh = (const uint4*)(Ah + (size_t)(mBase + cr) * ldA + goff);
            const uint4* pAl = (const uint4*)(Al + (size_t)(mBase + cr) * ldA + goff);
            const uint4* pBh = (const uint4*)(Bh + (size_t)(nBase + cr) * ldB + goff);
            const uint4* pBl = (const uint4*)(Bl + (size_t)(nBase + cr) * ldB + goff);
            uint4* dAh = (uint4*)(sAh + cr * LSTR + cs * 8);
            uint4* dAl = (uint4*)(sAl + cr * LSTR + cs * 8);
            uint4* dBh = (uint4*)(sBh + cr * LSTR + cs * 8);
            uint4* dBl = (uint4*)(sBl + cr * LSTR + cs * 8);
            dAh[0] = pAh[0]; dAh[1] = pAh[1];
            dAl[0] = pAl[0]; dAl[1] = pAl[1];
            dBh[0] = pBh[0]; dBh[1] = pBh[1];
            dBl[0] = pBl[0]; dBl[1] = pBl[1];
        }
        __syncthreads();

#pragma unroll
        for (int ks = 0; ks < 2; ks++) {
            uint32_t ah[2][4], al[2][4], bh[8][2], bl[8][2];
#pragma unroll
            for (int mt = 0; mt < 2; mt++) {
                const uint32_t off =
                    ((wm + mt * 16 + (lane & 15)) * LSTR + ks * 16 + (lane >> 4) * 8) * 2;
                ldsm4(ah[mt], uAh + off);
                ldsm4(al[mt], uAl + off);
            }
#pragma unroll
            for (int p = 0; p < 4; p++) {
                const uint32_t off =
                    ((wn + p * 16 + ((lane >> 4) & 1) * 8 + (lane & 7)) * LSTR +
                     ks * 16 + ((lane >> 3) & 1) * 8) * 2;
                uint32_t r4[4];
                ldsm4(r4, uBh + off);
                bh[2 * p][0] = r4[0]; bh[2 * p][1] = r4[1];
                bh[2 * p + 1][0] = r4[2]; bh[2 * p + 1][1] = r4[3];
                ldsm4(r4, uBl + off);
                bl[2 * p][0] = r4[0]; bl[2 * p][1] = r4[1];
                bl[2 * p + 1][0] = r4[2]; bl[2 * p + 1][1] = r4[3];
            }
#pragma unroll
            for (int mt = 0; mt < 2; mt++)
#pragma unroll
                for (int nt = 0; nt < 8; nt++) {
                    mma16816(acc[mt][nt], ah[mt], bh[nt]);
                    mma16816(acc[mt][nt], ah[mt], bl[nt]);
                    mma16816(acc[mt][nt], al[mt], bh[nt]);
                }
        }
        __syncthreads();
    }

    // epilogue: c-frag rows = lane>>2 (+8), cols = 2*(lane&3)+{0,1}
    const int erow = lane >> 2;
    const int ecol = (lane & 3) * 2;
#pragma unroll
    for (int mt = 0; mt < 2; mt++) {
#pragma unroll
        for (int nt = 0; nt < 8; nt++) {
            const int gn = nBase + wn + nt * 8 + ecol;
            if (gn >= nLimit) continue;
            float b0 = 0.f, b1 = 0.f;
            if (bias1) { b0 += bias1[gn]; b1 += bias1[gn + 1]; }
            if (bias2) { b0 += bias2[gn]; b1 += bias2[gn + 1]; }
            const int r0 = mBase + wm + mt * 16 + erow;
            const float v00 = acc[mt][nt][0] + b0, v01 = acc[mt][nt][1] + b1;
            const float v10 = acc[mt][nt][2] + b0, v11 = acc[mt][nt][3] + b1;
            if (C) {
                *(float2*)&C[(size_t)r0 * ldc + gn] = make_float2(v00, v01);
                *(float2*)&C[(size_t)(r0 + 8) * ldc + gn] = make_float2(v10, v11);
            }
            if (Chi) {
                const size_t i0 = (size_t)r0 * ldc + gn;
                const size_t i1 = (size_t)(r0 + 8) * ldc + gn;
                split_bf16(v00, &Chi[i0], &Clo[i0]);
                split_bf16(v01, &Chi[i0 + 1], &Clo[i0 + 1]);
                split_bf16(v10, &Chi[i1], &Clo[i1]);
                split_bf16(v11, &Chi[i1 + 1], &Clo[i1 + 1]);
            }
        }
    }
}

// ---------------- all input conversions + embedding gather ----------------
#define NB_GATH 8192     // 2,097,152 / 256
#define NB_OUTW 20000    // 5,120,000
#define NB_PTCH 18816    // 4,816,896
#define NB_KVW  1536     // 393,216
#define NB_AWK  1024     // 262,144
#define NB_WIH  4096     // 1,048,576
__global__ void gather_conv(const int* __restrict__ ids, const float* __restrict__ emb,
                            const float* __restrict__ outW, const float* __restrict__ patches,
                            const float* __restrict__ kvW, const float* __restrict__ aWk,
                            const float* __restrict__ Wih)
{
    int blk = blockIdx.x;
    const int tid = threadIdx.x;
    if (blk < NB_GATH) {
        const int i = blk * 256 + tid;
        const int d = i & (DH - 1);
        const int bt = i >> 9;
        split_bf16(emb[(size_t)ids[bt] * DH + d], &g_x_hi[i], &g_x_lo[i]);
        return;
    }
    blk -= NB_GATH;
    if (blk < NB_OUTW) {
        const int j = blk * 256 + tid;
        if (j < VV * DH) split_bf16(outW[j], &g_w_hi[j], &g_w_lo[j]);
        return;
    }
    blk -= NB_OUTW;
    if (blk < NB_PTCH) {
        const int j = blk * 256 + tid;
        split_bf16(patches[j], &g_p_hi[j], &g_p_lo[j]);
        return;
    }
    blk -= NB_PTCH;
    if (blk < NB_KVW) {
        const int j = blk * 256 + tid;
        split_bf16(kvW[j], &g_kvw_hi[j], &g_kvw_lo[j]);
        return;
    }
    blk -= NB_KVW;
    if (blk < NB_AWK) {
        const int j = blk * 256 + tid;
        split_bf16(aWk[j], &g_awk_hi[j], &g_awk_lo[j]);
        return;
    }
    blk -= NB_AWK;
    {
        const int j = blk * 256 + tid;             // Wih x-half: rows 2048, cols 0..511
        const int r = j >> 9, c = j & 511;
        split_bf16(Wih[(size_t)r * 1024 + c], &g_wih_hi[j], &g_wih_lo[j]);
    }
}

// ---------------- persistent decode loop (unchanged from R9-pass) ----------------
__global__ __launch_bounds__(256, 1) void decode_loop(
    const float* __restrict__ Wh, const float* __restrict__ av,
    const float* __restrict__ Wih, const float* __restrict__ Whh,
    const float* __restrict__ lnw, const float* __restrict__ lnb,
    const float* __restrict__ cls,
    const float* __restrict__ ihW, const float* __restrict__ ihb,
    const float* __restrict__ icW, const float* __restrict__ icb)
{
    extern __shared__ float smem[];
    float* wH = smem;                                  // [NH][512]
    float* wX = smem + NH * 512;                       // [NX][512]
    float4* hs4 = (float4*)(smem + (NH + NX) * 512);   // [32][HSTR4]

    __shared__ float s_v[512];
    __shared__ float s_hwh[512];
    __shared__ float s_sc[49];
    __shared__ float s_e[64];
    __shared__ float s_r0[8], s_r1[8], s_mv[2];

    const int tid = threadIdx.x;
    const int bid = blockIdx.x;
    const int warp = tid >> 5, lane = tid & 31;
    const int gwarp = bid * 8 + warp;
    const int b32 = tid & 31, q = tid >> 5;
    unsigned bt = 0;

#pragma unroll
    for (int i = 0; i < NH; i++) {
        const int r = bid * NH + i;
        const float* src = (r < 2048) ? (Whh + (size_t)r * 512)
                          : (r < 2560) ? (Wh + (size_t)(r - 2048) * 512) : nullptr;
        if (src) for (int k = tid; k < 512; k += 256) wH[i * 512 + k] = src[k];
    }
#pragma unroll
    for (int i = 0; i < NX; i++) {
        const int r = bid * NX + i;
        if (r < 2048)
            for (int k = tid; k < 512; k += 256) wX[i * 512 + k] = Wih[(size_t)r * 1024 + 512 + k];
    }
    for (int k = tid; k < 512; k += 256) s_v[k] = av[k];

    auto gsync = [&](unsigned target) {
        __syncthreads();
        if (tid == 0) {
            __threadfence();
            unsigned a = atomicAdd(&g_sync[0], 1u);
            if (a == target * GRID_P - 1u) {
                atomicExch(&g_sync[1], target);
            } else {
                while (*(volatile unsigned*)&g_sync[1] < target) {}
            }
            __threadfence();
        }
        __syncthreads();
    };

    // ---- h0/c0 (folded) ----
    for (int j = gwarp; j < 2 * BB * DH; j += GRID_P * 8) {
        const int sel = (j >= BB * DH);
        const int r = sel ? j - BB * DH : j;
        const int b = r >> 9, d = r & (DH - 1);
        const float4* W4 = (const float4*)((sel ? icW : ihW) + (size_t)d * 768);
        const float4* x4 = (const float4*)(cls + (size_t)b * 768);
        float acc = 0.f;
#pragma unroll
        for (int p = 0; p < 6; p++) {
            float4 w = W4[lane + 32 * p];
            float4 x = x4[lane + 32 * p];
            acc += w.x * x.x + w.y * x.y + w.z * x.z + w.w * x.w;
        }
#pragma unroll
        for (int o = 16; o; o >>= 1) acc += __shfl_xor_sync(0xffffffffu, acc, o);
        if (lane == 0) {
            if (sel) g_c[b * DH + d] = acc + icb[d];
            else     g_h[b * DH + d] = acc + ihb[d];
        }
    }
    gsync(++bt);

    for (int t = 0; t < TT; t++) {
        // ======== Phase W: h-gates + hwh (weights in smem) ========
        {
            const float4* hsrc = (const float4*)g_h;
            for (int idx = tid; idx < 32 * 128; idx += 256)
                hs4[(idx >> 7) * HSTR4 + (idx & 127)] = hsrc[idx];
        }
        __syncthreads();
        {
            const float4* hp = hs4 + b32 * HSTR4;
            float4 a0 = make_float4(0.f, 0.f, 0.f, 0.f), a1 = a0, a2 = a0;
            const float4* w0 = (const float4*)(wH + q * 512);
            const float4* w1 = (const float4*)(wH + (q + 8) * 512);
            const float4* w2 = (const float4*)(wH + ((q < 2) ? (q + 16) : 0) * 512);
#pragma unroll 8
            for (int k = 0; k < 128; k++) {
                const float4 h = hp[k];
                const float4 x = w0[k];
                a0.x = fmaf(h.x, x.x, a0.x); a0.y = fmaf(h.y, x.y, a0.y);
                a0.z = fmaf(h.z, x.z, a0.z); a0.w = fmaf(h.w, x.w, a0.w);
                const float4 y = w1[k];
                a1.x = fmaf(h.x, y.x, a1.x); a1.y = fmaf(h.y, y.y, a1.y);
                a1.z = fmaf(h.z, y.z, a1.z); a1.w = fmaf(h.w, y.w, a1.w);
                const float4 z = w2[k];
                a2.x = fmaf(h.x, z.x, a2.x); a2.y = fmaf(h.y, z.y, a2.y);
                a2.z = fmaf(h.z, z.z, a2.z); a2.w = fmaf(h.w, z.w, a2.w);
            }
            const float s0 = (a0.x + a0.y) + (a0.z + a0.w);
            const float s1 = (a1.x + a1.y) + (a1.z + a1.w);
            const float s2 = (a2.x + a2.y) + (a2.z + a2.w);
            int r = bid * NH + q;
            if (r < 2048) g_gh[b32 * 2048 + r] = s0;
            else if (r < 2560) g_hwh[b32 * 512 + r - 2048] = s0;
            r = bid * NH + q + 8;
            if (r < 2048) g_gh[b32 * 2048 + r] = s1;
            else if (r < 2560) g_hwh[b32 * 512 + r - 2048] = s1;
            if (q < 2) {
                r = bid * NH + q + 16;
                if (r < 2048) g_gh[b32 * 2048 + r] = s2;
                else if (r < 2560) g_hwh[b32 * 512 + r - 2048] = s2;
            }
        }
        gsync(++bt);

        // ======== Phase B: chunk scores + partial ctx + per-b combine ========
        if (bid < BB * 4) {
            const int b = bid >> 2, p = bid & 3;
            for (int k = tid; k < 512; k += 256) s_hwh[k] = g_hwh[b * 512 + k];
            __syncthreads();

            for (int n = warp; n < 49; n += 8) {
                const int ng = p * 49 + n;
                const float4* wk4 = (const float4*)(g_wk + ((size_t)(b * NN + ng)) * 512);
                const float4* hw4 = (const float4*)s_hwh;
                const float4* v4  = (const float4*)s_v;
                float s = 0.f;
#pragma unroll
                for (int i = 0; i < 4; i++) {
                    const float4 a = wk4[lane + 32 * i];
                    const float4 c = hw4[lane + 32 * i];
                    const float4 w = v4[lane + 32 * i];
                    s += fast_tanh(a.x + c.x) * w.x + fast_tanh(a.y + c.y) * w.y +
                         fast_tanh(a.z + c.z) * w.z + fast_tanh(a.w + c.w) * w.w;
                }
#pragma unroll
                for (int o = 16; o; o >>= 1) s += __shfl_xor_sync(0xffffffffu, s, o);
                if (lane == 0) s_sc[n] = s;
            }
            __syncthreads();

            if (warp == 0) {
                const float x0 = (lane < 49) ? s_sc[lane] : -1e30f;
                const float x1 = (lane + 32 < 49) ? s_sc[lane + 32] : -1e30f;
                float m = fmaxf(x0, x1);
#pragma unroll
                for (int o = 16; o; o >>= 1) m = fmaxf(m, __shfl_xor_sync(0xffffffffu, m, o));
                const float e0 = (lane < 49) ? __expf(x0 - m) : 0.f;
                const float e1 = (lane + 32 < 49) ? __expf(x1 - m) : 0.f;
                if (lane < 49) s_e[lane] = e0;
                if (lane + 32 < 49) s_e[lane + 32] = e1;
                float su = e0 + e1;
#pragma unroll
                for (int o = 16; o; o >>= 1) su += __shfl_xor_sync(0xffffffffu, su, o);
                if (lane == 0) { g_cm[b * 4 + p] = m; g_cs[b * 4 + p] = su; }
            }
            __syncthreads();

#pragma unroll
            for (int u = 0; u < 2; u++) {
                const int d = tid + 256 * u;
                const float* Kp = g_keys + ((size_t)(b * NN + p * 49)) * 512 + d;
                float a = 0.f;
#pragma unroll 7
                for (int i = 0; i < 49; i++) a = fmaf(s_e[i], Kp[(size_t)i * 512], a);
                g_ctxp[p][b * 512 + d] = a;
            }

            __syncthreads();
            if (tid == 0) {
                __threadfence();
                atomicAdd(&g_sync[2 + b * 32], 1u);
                while (*(volatile unsigned*)&g_sync[2 + b * 32] < 4u * (unsigned)(t + 1)) {}
                __threadfence();
            }
            __syncthreads();

            if (tid < 128) {
                const int d = p * 128 + tid;
                const float m0 = g_cm[b*4+0], m1 = g_cm[b*4+1], m2 = g_cm[b*4+2], m3 = g_cm[b*4+3];
                const float m = fmaxf(fmaxf(m0, m1), fmaxf(m2, m3));
                const float e0 = __expf(m0 - m), e1 = __expf(m1 - m);
                const float e2 = __expf(m2 - m), e3 = __expf(m3 - m);
                const float den = e0 * g_cs[b*4+0] + e1 * g_cs[b*4+1] +
                                  e2 * g_cs[b*4+2] + e3 * g_cs[b*4+3];
                const float v = e0 * g_ctxp[0][b*512+d] + e1 * g_ctxp[1][b*512+d] +
                                e2 * g_ctxp[2][b*512+d] + e3 * g_ctxp[3][b*512+d];
                g_ctx[b * 512 + d] = v / den;
            }
        }
        gsync(++bt);

        // ======== Phase C: ctx-gates (weights in smem) ========
        {
            const float4* csrc = (const float4*)g_ctx;
            for (int idx = tid; idx < 32 * 128; idx += 256)
                hs4[(idx >> 7) * HSTR4 + (idx & 127)] = csrc[idx];
        }
        __syncthreads();
        {
            const float4* cp = hs4 + b32 * HSTR4;
            float4 a0 = make_float4(0.f, 0.f, 0.f, 0.f), a1 = a0;
            const float4* w0 = (const float4*)(wX + q * 512);
            const float4* w1 = (const float4*)(wX + ((q + 8 < NX) ? (q + 8) : 0) * 512);
#pragma unroll 8
            for (int k = 0; k < 128; k++) {
                const float4 h = cp[k];
                const float4 x = w0[k];
                a0.x = fmaf(h.x, x.x, a0.x); a0.y = fmaf(h.y, x.y, a0.y);
                a0.z = fmaf(h.z, x.z, a0.z); a0.w = fmaf(h.w, x.w, a0.w);
                const float4 y = w1[k];
                a1.x = fmaf(h.x, y.x, a1.x); a1.y = fmaf(h.y, y.y, a1.y);
                a1.z = fmaf(h.z, y.z, a1.z); a1.w = fmaf(h.w, y.w, a1.w);
            }
            const float s0 = (a0.x + a0.y) + (a0.z + a0.w);
            const float s1 = (a1.x + a1.y) + (a1.z + a1.w);
            int r = bid * NX + q;
            if (r < 2048) g_gx[b32 * 2048 + r] = s0;
            if (q + 8 < NX) {
                r = bid * NX + q + 8;
                if (r < 2048) g_gx[b32 * 2048 + r] = s1;
            }
        }
        gsync(++bt);

        // ======== Phase D: cell + LayerNorm (32 blocks) ========
        if (bid < BB) {
            const int b = bid;
            const float* Gx = g_Gx + ((size_t)(b * TT + t)) * 2048;
            const float* Gh = g_gh + (size_t)b * 2048;
            const float* Gc = g_gx + (size_t)b * 2048;
            float hr[2];
            float sum = 0.f, ssq = 0.f;
#pragma unroll
            for (int u = 0; u < 2; u++) {
                const int d = tid + 256 * u;
                const float gi = Gx[d]        + Gh[d]        + Gc[d];
                const float gf = Gx[512 + d]  + Gh[512 + d]  + Gc[512 + d];
                const float gg = Gx[1024 + d] + Gh[1024 + d] + Gc[1024 + d];
                const float go = Gx[1536 + d] + Gh[1536 + d] + Gc[1536 + d];
                const float c_old = g_c[b * DH + d];
                const float cn = sigm(gf) * c_old + sigm(gi) * tanhf(gg);
                g_c[b * DH + d] = cn;
                const float h = sigm(go) * tanhf(cn);
                hr[u] = h; sum += h; ssq += h * h;
            }
#pragma unroll
            for (int o = 16; o; o >>= 1) {
                sum += __shfl_xor_sync(0xffffffffu, sum, o);
                ssq += __shfl_xor_sync(0xffffffffu, ssq, o);
            }
            if (lane == 0) { s_r0[warp] = sum; s_r1[warp] = ssq; }
            __syncthreads();
            if (tid < 8) {
                float s = s_r0[tid], qq = s_r1[tid];
#pragma unroll
                for (int o = 4; o; o >>= 1) {
                    s += __shfl_xor_sync(0x000000ffu, s, o);
                    qq += __shfl_xor_sync(0x000000ffu, qq, o);
                }
                if (tid == 0) { s_mv[0] = s * (1.f / DH); s_mv[1] = qq * (1.f / DH); }
            }
            __syncthreads();
            const float mu = s_mv[0];
            const float var = s_mv[1] - mu * mu;
            const float rstd = rsqrtf(var + 1e-5f);
#pragma unroll
            for (int u = 0; u < 2; u++) {
                const int d = tid + 256 * u;
                const float h = (hr[u] - mu) * rstd * lnw[d] + lnb[d];
                g_h[b * DH + d] = h;
                const size_t idx = ((size_t)(b * TT + t)) * DH + d;
                split_bf16(h, &g_hall_hi[idx], &g_hall_lo[idx]);
            }
        }
        gsync(++bt);
    }
}

// ---------------- launch ----------------
extern "C" void kernel_launch(void* const* d_in, const int* in_sizes, int n_in,
                              void* d_out, int out_size)
{
    const float* patches = (const float*)d_in[0];
    const float* cls     = (const float*)d_in[1];
    const int*   tgt     = (const int*)  d_in[2];
    const float* emb     = (const float*)d_in[3];
    const float* kvW     = (const float*)d_in[4];
    const float* kvb     = (const float*)d_in[5];
    const float* ihW     = (const float*)d_in[6];
    const float* ihb     = (const float*)d_in[7];
    const float* icW     = (const float*)d_in[8];
    const float* icb     = (const float*)d_in[9];
    const float* aWh     = (const float*)d_in[10];
    const float* aWk     = (const float*)d_in[11];
    const float* av      = (const float*)d_in[12];
    const float* Wih     = (const float*)d_in[13];
    const float* Whh     = (const float*)d_in[14];
    const float* bih     = (const float*)d_in[15];
    const float* bhh     = (const float*)d_in[16];
    const float* lnw     = (const float*)d_in[17];
    const float* lnb     = (const float*)d_in[18];
    const float* outW    = (const float*)d_in[19];
    const float* outb    = (const float*)d_in[20];
    float* out = (float*)d_out;

    float *keys, *wk, *Gx;
    bf16 *xh, *xl, *ph, *pl, *kvh, *kvl, *awh, *awl, *wih_h, *wih_l;
    bf16 *kh, *kl, *hh, *hl, *wh, *wl;
    unsigned* syncp;
    cudaGetSymbolAddress((void**)&keys, g_keys);
    cudaGetSymbolAddress((void**)&wk,   g_wk);
    cudaGetSymbolAddress((void**)&Gx,   g_Gx);
    cudaGetSymbolAddress((void**)&syncp, g_sync);
    cudaGetSymbolAddress((void**)&xh, g_x_hi);   cudaGetSymbolAddress((void**)&xl, g_x_lo);
    cudaGetSymbolAddress((void**)&ph, g_p_hi);   cudaGetSymbolAddress((void**)&pl, g_p_lo);
    cudaGetSymbolAddress((void**)&kvh, g_kvw_hi); cudaGetSymbolAddress((void**)&kvl, g_kvw_lo);
    cudaGetSymbolAddress((void**)&awh, g_awk_hi); cudaGetSymbolAddress((void**)&awl, g_awk_lo);
    cudaGetSymbolAddress((void**)&wih_h, g_wih_hi); cudaGetSymbolAddress((void**)&wih_l, g_wih_lo);
    cudaGetSymbolAddress((void**)&kh, g_keys_hi); cudaGetSymbolAddress((void**)&kl, g_keys_lo);
    cudaGetSymbolAddress((void**)&hh, g_hall_hi); cudaGetSymbolAddress((void**)&hl, g_hall_lo);
    cudaGetSymbolAddress((void**)&wh, g_w_hi);    cudaGetSymbolAddress((void**)&wl, g_w_lo);

    cudaMemsetAsync(syncp, 0, (2 + BB * 32) * sizeof(unsigned));

    cudaFuncSetAttribute(decode_loop, cudaFuncAttributeMaxDynamicSharedMemorySize,
                         DYN_FLOATS * (int)sizeof(float));

    gather_conv<<<NB_GATH + NB_OUTW + NB_PTCH + NB_KVW + NB_AWK + NB_WIH, 256>>>(
        tgt, emb, outW, patches, kvW, aWk, Wih);

    // keys = patches @ kvW^T + kvb     [6272 x 512], K=768 (also emit bf16 split)
    mma_nt<<<dim3(4, 49), 256>>>(ph, pl, kvh, kvl, kvb, nullptr,
                                 keys, 512, 512, 24, 768, 768, kh, kl);
    // wk = keys @ aWk^T                [6272 x 512], K=512
    mma_nt<<<dim3(4, 49), 256>>>(kh, kl, awh, awl, nullptr, nullptr,
                                 wk, 512, 512, 16, 512, 512, nullptr, nullptr);
    // Gx = x @ Wih_x^T + b_ih + b_hh   [4096 x 2048], K=512
    mma_nt<<<dim3(16, 32), 256>>>(xh, xl, wih_h, wih_l, bih, bhh,
                                  Gx, 2048, 2048, 16, 512, 512, nullptr, nullptr);

    decode_loop<<<GRID_P, 256, DYN_FLOATS * sizeof(float)>>>(
        aWh, av, Wih, Whh, lnw, lnb, cls, ihW, ihb, icW, icb);

    // logits = hall @ outW^T + outb    [4096 x 10000], K=512
    mma_nt<<<dim3(79, 32), 256>>>(hh, hl, wh, wl, outb, nullptr,
                                  out, VV, VV, 16, 512, 512, nullptr, nullptr);
}